// round 5
// baseline (speedup 1.0000x reference)
#include <cuda_runtime.h>
#include <math.h>

// Problem constants
#define Bn 4
#define Tn 2048
#define Cn 1024
#define Hn 16
#define HSn 64
#define Mn (Bn * Tn)        // 8192 rows
#define FFn (4 * Cn)        // 4096

// ---------------------------------------------------------------------------
// Scratch (device globals -- no allocation allowed in kernel_launch)
// ---------------------------------------------------------------------------
__device__ float g_x1[8388608];    // [M, C]  LN1 output
__device__ float g_qkv[25165824];  // [M, 3C] q|k|v, col = which*1024 + h*64 + d
__device__ float g_o[8388608];     // [M, C]  attention output (head-concat)
__device__ float g_x2[8388608];    // [M, C]  x1 + o@Wp + bp
__device__ float g_x3[8388608];    // [M, C]  LN2 output
__device__ float g_hb[33554432];   // [M, 4C] relu(x3@W1+b1)
__device__ float g_wqkv[3145728];  // [C, 3C] packed Wq|Wk|Wv

// ---------------------------------------------------------------------------
// LayerNorm: one block per row (C=1024, 256 threads x float4)
// ---------------------------------------------------------------------------
__global__ void ln_kernel(const float* __restrict__ x, const float* __restrict__ g,
                          const float* __restrict__ beta, float* __restrict__ y)
{
    const int row = blockIdx.x;
    const int t = threadIdx.x;
    const float4 v = reinterpret_cast<const float4*>(x + (size_t)row * Cn)[t];
    float s = v.x + v.y + v.z + v.w;
    float q = v.x * v.x + v.y * v.y + v.z * v.z + v.w * v.w;
#pragma unroll
    for (int off = 16; off; off >>= 1) {
        s += __shfl_xor_sync(0xffffffffu, s, off);
        q += __shfl_xor_sync(0xffffffffu, q, off);
    }
    __shared__ float ss[8], qs[8];
    if ((t & 31) == 0) { ss[t >> 5] = s; qs[t >> 5] = q; }
    __syncthreads();
    s = 0.f; q = 0.f;
#pragma unroll
    for (int i = 0; i < 8; i++) { s += ss[i]; q += qs[i]; }
    const float mu = s * (1.0f / Cn);
    const float var = q * (1.0f / Cn) - mu * mu;
    const float rstd = rsqrtf(var + 1e-5f);
    const float4 gv = reinterpret_cast<const float4*>(g)[t];
    const float4 bv = reinterpret_cast<const float4*>(beta)[t];
    float4 o;
    o.x = (v.x - mu) * rstd * gv.x + bv.x;
    o.y = (v.y - mu) * rstd * gv.y + bv.y;
    o.z = (v.z - mu) * rstd * gv.z + bv.z;
    o.w = (v.w - mu) * rstd * gv.w + bv.w;
    reinterpret_cast<float4*>(y + (size_t)row * Cn)[t] = o;
}

// ---------------------------------------------------------------------------
// Pack Wq/Wk/Wv ([H,C,HS] each) into one [C, 3C] GEMM-friendly matrix.
// out[k, which*1024 + h*64 + d] = W[h, k, d]
// ---------------------------------------------------------------------------
__global__ void pack_wqkv_kernel(const float* __restrict__ Wq, const float* __restrict__ Wk,
                                 const float* __restrict__ Wv, float* __restrict__ out)
{
    const int k = blockIdx.y;                       // 0..1023
    const int j = blockIdx.x * 256 + threadIdx.x;   // 0..3071
    const int which = j >> 10;
    const int jj = j & 1023;
    const int h = jj >> 6, d = jj & 63;
    const float* W = (which == 0) ? Wq : (which == 1) ? Wk : Wv;
    out[(size_t)k * 3072 + j] = W[((size_t)h * Cn + k) * HSn + d];
}

// ---------------------------------------------------------------------------
// SGEMM: C[M,N] = A[M,K] @ B[K,N] (+bias[n]) (+res[m,n]) (relu)
// BM=BN=128, BK=16, 256 threads, 8x8 microtile, double-buffered smem.
// Requires M%128==0, N%128==0, K%16==0 (all true for our shapes).
// ---------------------------------------------------------------------------
template <bool BIAS, bool RES, bool RELU>
__global__ __launch_bounds__(256) void sgemm_kernel(
    const float* __restrict__ A, const float* __restrict__ Bm,
    const float* __restrict__ bias, const float* __restrict__ res,
    float* __restrict__ C, int Mdim, int Ndim, int Kdim)
{
    constexpr int BM = 128, BN = 128, BK = 16;
    __shared__ __align__(16) float As[2][BK][BM];
    __shared__ __align__(16) float Bs[2][BK][BN];

    const int tid = threadIdx.x;
    const int tx = tid & 15, ty = tid >> 4;
    const int m0 = blockIdx.y * BM;
    const int n0 = blockIdx.x * BN;

    // global load mapping
    const int arow = tid >> 2;            // 0..63 (+64 for second half)
    const int acol = (tid & 3) << 2;      // 0,4,8,12
    const int brow = tid >> 5;            // 0..7 (+8)
    const int bcol = (tid & 31) << 2;     // 0..124

    const float* Ag = A + (size_t)m0 * Kdim;
    const float* Bg = Bm + n0;

    float4 ra0, ra1, rb0, rb1;

    auto gload = [&](int kt) {
        ra0 = *reinterpret_cast<const float4*>(Ag + (size_t)(arow)      * Kdim + kt * BK + acol);
        ra1 = *reinterpret_cast<const float4*>(Ag + (size_t)(arow + 64) * Kdim + kt * BK + acol);
        rb0 = *reinterpret_cast<const float4*>(Bg + (size_t)(kt * BK + brow)     * Ndim + bcol);
        rb1 = *reinterpret_cast<const float4*>(Bg + (size_t)(kt * BK + brow + 8) * Ndim + bcol);
    };
    auto sstore = [&](int buf) {
        As[buf][acol + 0][arow] = ra0.x; As[buf][acol + 1][arow] = ra0.y;
        As[buf][acol + 2][arow] = ra0.z; As[buf][acol + 3][arow] = ra0.w;
        As[buf][acol + 0][arow + 64] = ra1.x; As[buf][acol + 1][arow + 64] = ra1.y;
        As[buf][acol + 2][arow + 64] = ra1.z; As[buf][acol + 3][arow + 64] = ra1.w;
        *reinterpret_cast<float4*>(&Bs[buf][brow][bcol])     = rb0;
        *reinterpret_cast<float4*>(&Bs[buf][brow + 8][bcol]) = rb1;
    };

    float acc[8][8];
#pragma unroll
    for (int i = 0; i < 8; i++)
#pragma unroll
        for (int j = 0; j < 8; j++) acc[i][j] = 0.f;

    gload(0);
    sstore(0);
    __syncthreads();

    const int nk = Kdim / BK;
    int buf = 0;
    for (int kt = 0; kt < nk; kt++) {
        if (kt + 1 < nk) gload(kt + 1);
#pragma unroll
        for (int k = 0; k < BK; k++) {
            const float4 a0 = *reinterpret_cast<const float4*>(&As[buf][k][ty * 8]);
            const float4 a1 = *reinterpret_cast<const float4*>(&As[buf][k][ty * 8 + 4]);
            const float4 b0 = *reinterpret_cast<const float4*>(&Bs[buf][k][tx * 8]);
            const float4 b1 = *reinterpret_cast<const float4*>(&Bs[buf][k][tx * 8 + 4]);
            const float av[8] = {a0.x, a0.y, a0.z, a0.w, a1.x, a1.y, a1.z, a1.w};
            const float bv[8] = {b0.x, b0.y, b0.z, b0.w, b1.x, b1.y, b1.z, b1.w};
#pragma unroll
            for (int i = 0; i < 8; i++)
#pragma unroll
                for (int j = 0; j < 8; j++) acc[i][j] += av[i] * bv[j];
        }
        if (kt + 1 < nk) {
            sstore(buf ^ 1);
            __syncthreads();
            buf ^= 1;
        }
    }

    // epilogue
#pragma unroll
    for (int i = 0; i < 8; i++) {
        const int m = m0 + ty * 8 + i;
#pragma unroll
        for (int jq = 0; jq < 2; jq++) {
            const int n = n0 + tx * 8 + jq * 4;
            float4 v;
            v.x = acc[i][jq * 4 + 0]; v.y = acc[i][jq * 4 + 1];
            v.z = acc[i][jq * 4 + 2]; v.w = acc[i][jq * 4 + 3];
            if (BIAS) {
                const float4 bb = *reinterpret_cast<const float4*>(bias + n);
                v.x += bb.x; v.y += bb.y; v.z += bb.z; v.w += bb.w;
            }
            if (RES) {
                const float4 rr = *reinterpret_cast<const float4*>(res + (size_t)m * Ndim + n);
                v.x += rr.x; v.y += rr.y; v.z += rr.z; v.w += rr.w;
            }
            if (RELU) {
                v.x = fmaxf(v.x, 0.f); v.y = fmaxf(v.y, 0.f);
                v.z = fmaxf(v.z, 0.f); v.w = fmaxf(v.w, 0.f);
            }
            *reinterpret_cast<float4*>(C + (size_t)m * Ndim + n) = v;
        }
    }
}

// ---------------------------------------------------------------------------
// Causal flash attention (fp32). One block per (query-tile of 128, head, batch).
// Q/K stored d-major in smem for vectorized fragment loads.
// scale = C^-0.5 = 1/32 (reference uses n_embed, not head_size).
// ---------------------------------------------------------------------------
__global__ __launch_bounds__(256, 2) void flash_kernel(const float* __restrict__ qkv,
                                                       float* __restrict__ o)
{
    extern __shared__ float sm[];
    float* Qt = sm;                  // [64][128]  Qt[d*128 + r]
    float* Kt = Qt + 64 * 128;       // [64][64]   Kt[d*64  + c]
    float* Vs = Kt + 64 * 64;        // [64][64]   Vs[k*64  + d]
    float* Ps = Vs + 64 * 64;        // [128][68]  Ps[r*68  + k] (padded)

    const int t  = threadIdx.x;
    const int tx = t & 15, ty = t >> 4;
    const int qi = (int)gridDim.x - 1 - (int)blockIdx.x;  // big tiles first
    const int h  = blockIdx.y, b = blockIdx.z;
    const int q0 = qi * 128;

    const float* Qg = qkv + ((size_t)(b * Tn + q0)) * 3072 + h * 64;
    const float* Kg = qkv + ((size_t)(b * Tn)) * 3072 + 1024 + h * 64;
    const float* Vg = Kg + 1024;

    // load Q tile transposed (d-major)
#pragma unroll
    for (int u = 0; u < 8; u++) {
        const int f = t + 256 * u;
        const int r = f >> 4, d = (f & 15) << 2;
        const float4 v = *reinterpret_cast<const float4*>(Qg + (size_t)r * 3072 + d);
        Qt[(d + 0) * 128 + r] = v.x;
        Qt[(d + 1) * 128 + r] = v.y;
        Qt[(d + 2) * 128 + r] = v.z;
        Qt[(d + 3) * 128 + r] = v.w;
    }

    float oacc[8][4];
    float m[8], l[8];
#pragma unroll
    for (int i = 0; i < 8; i++) {
        m[i] = -1e30f; l[i] = 0.f;
#pragma unroll
        for (int j = 0; j < 4; j++) oacc[i][j] = 0.f;
    }

    const int ntiles = 2 * qi + 2;
    for (int jt = 0; jt < ntiles; jt++) {
        const int j0 = jt * 64;
        __syncthreads();  // prev PV reads done before K/V overwrite
        // load K (transposed) and V tiles
#pragma unroll
        for (int u = 0; u < 4; u++) {
            const int f = t + 256 * u;
            const int c = f >> 4, d = (f & 15) << 2;
            const float4 kv = *reinterpret_cast<const float4*>(Kg + (size_t)(j0 + c) * 3072 + d);
            Kt[(d + 0) * 64 + c] = kv.x;
            Kt[(d + 1) * 64 + c] = kv.y;
            Kt[(d + 2) * 64 + c] = kv.z;
            Kt[(d + 3) * 64 + c] = kv.w;
            const float4 vv = *reinterpret_cast<const float4*>(Vg + (size_t)(j0 + c) * 3072 + d);
            *reinterpret_cast<float4*>(Vs + c * 64 + d) = vv;
        }
        __syncthreads();

        // S = Q @ K^T
        float s[8][4];
#pragma unroll
        for (int i = 0; i < 8; i++)
#pragma unroll
            for (int j = 0; j < 4; j++) s[i][j] = 0.f;

#pragma unroll 4
        for (int d = 0; d < 64; d++) {
            const float4 a0 = *reinterpret_cast<const float4*>(Qt + d * 128 + ty * 8);
            const float4 a1 = *reinterpret_cast<const float4*>(Qt + d * 128 + ty * 8 + 4);
            const float4 bb = *reinterpret_cast<const float4*>(Kt + d * 64 + tx * 4);
            const float av[8] = {a0.x, a0.y, a0.z, a0.w, a1.x, a1.y, a1.z, a1.w};
            const float bw[4] = {bb.x, bb.y, bb.z, bb.w};
#pragma unroll
            for (int i = 0; i < 8; i++)
#pragma unroll
                for (int j = 0; j < 4; j++) s[i][j] += av[i] * bw[j];
        }

        // scale + causal mask
#pragma unroll
        for (int i = 0; i < 8; i++) {
            const int q = q0 + ty * 8 + i;
#pragma unroll
            for (int j = 0; j < 4; j++) {
                const int key = j0 + tx * 4 + j;
                s[i][j] = (key <= q) ? s[i][j] * 0.03125f : -1e30f;
            }
        }

        // online softmax (rows span 16 lanes with same ty -> shfl over xor 1..8)
#pragma unroll
        for (int i = 0; i < 8; i++) {
            float mt = fmaxf(fmaxf(s[i][0], s[i][1]), fmaxf(s[i][2], s[i][3]));
#pragma unroll
            for (int off = 8; off; off >>= 1)
                mt = fmaxf(mt, __shfl_xor_sync(0xffffffffu, mt, off));
            const float mn = fmaxf(m[i], mt);
            const float corr = __expf(m[i] - mn);
            float rs = 0.f;
#pragma unroll
            for (int j = 0; j < 4; j++) {
                const float p = __expf(s[i][j] - mn);
                s[i][j] = p; rs += p;
            }
#pragma unroll
            for (int off = 8; off; off >>= 1)
                rs += __shfl_xor_sync(0xffffffffu, rs, off);
            l[i] = l[i] * corr + rs;
            m[i] = mn;
#pragma unroll
            for (int j = 0; j < 4; j++) oacc[i][j] *= corr;
        }

        // P -> smem
#pragma unroll
        for (int i = 0; i < 8; i++)
#pragma unroll
            for (int j = 0; j < 4; j++)
                Ps[(ty * 8 + i) * 68 + tx * 4 + j] = s[i][j];
        __syncthreads();

        // O += P @ V
#pragma unroll 4
        for (int k = 0; k < 64; k++) {
            const float4 vv = *reinterpret_cast<const float4*>(Vs + k * 64 + tx * 4);
            const float bw[4] = {vv.x, vv.y, vv.z, vv.w};
            float av[8];
#pragma unroll
            for (int i = 0; i < 8; i++) av[i] = Ps[(ty * 8 + i) * 68 + k];
#pragma unroll
            for (int i = 0; i < 8; i++)
#pragma unroll
                for (int j = 0; j < 4; j++) oacc[i][j] += av[i] * bw[j];
        }
    }

    // normalize + write head-concat output layout [B,T,C]
    float* Og = o + ((size_t)(b * Tn + q0)) * Cn + h * 64;
#pragma unroll
    for (int i = 0; i < 8; i++) {
        const float inv = 1.0f / l[i];
        const int r = ty * 8 + i;
        float4 v;
        v.x = oacc[i][0] * inv; v.y = oacc[i][1] * inv;
        v.z = oacc[i][2] * inv; v.w = oacc[i][3] * inv;
        *reinterpret_cast<float4*>(Og + (size_t)r * Cn + tx * 4) = v;
    }
}

// ---------------------------------------------------------------------------
// Launch sequence
// ---------------------------------------------------------------------------
extern "C" void kernel_launch(void* const* d_in, const int* in_sizes, int n_in,
                              void* d_out, int out_size)
{
    const float* x   = (const float*)d_in[0];
    const float* Wq  = (const float*)d_in[1];
    const float* Wk  = (const float*)d_in[2];
    const float* Wv  = (const float*)d_in[3];
    const float* Wp  = (const float*)d_in[4];
    const float* bp  = (const float*)d_in[5];
    const float* W1  = (const float*)d_in[6];
    const float* b1  = (const float*)d_in[7];
    const float* W2  = (const float*)d_in[8];
    const float* b2  = (const float*)d_in[9];
    const float* g1  = (const float*)d_in[10];
    const float* be1 = (const float*)d_in[11];
    const float* g2  = (const float*)d_in[12];
    const float* be2 = (const float*)d_in[13];
    float* out = (float*)d_out;

    float *x1, *qkv, *o, *x2, *x3, *hb, *wqkv;
    cudaGetSymbolAddress((void**)&x1,   g_x1);
    cudaGetSymbolAddress((void**)&qkv,  g_qkv);
    cudaGetSymbolAddress((void**)&o,    g_o);
    cudaGetSymbolAddress((void**)&x2,   g_x2);
    cudaGetSymbolAddress((void**)&x3,   g_x3);
    cudaGetSymbolAddress((void**)&hb,   g_hb);
    cudaGetSymbolAddress((void**)&wqkv, g_wqkv);

    constexpr int FLASH_SMEM = (64 * 128 + 64 * 64 + 64 * 64 + 128 * 68) * 4; // 100352 B
    cudaFuncSetAttribute(flash_kernel, cudaFuncAttributeMaxDynamicSharedMemorySize, FLASH_SMEM);

    // 1. LN1
    ln_kernel<<<Mn, 256>>>(x, g1, be1, x1);
    // 2. pack QKV weights
    pack_wqkv_kernel<<<dim3(12, 1024), 256>>>(Wq, Wk, Wv, wqkv);
    // 3. QKV GEMM: [8192,1024] @ [1024,3072]
    sgemm_kernel<false, false, false><<<dim3(24, 64), 256>>>(x1, wqkv, nullptr, nullptr, qkv, Mn, 3 * Cn, Cn);
    // 4. causal flash attention
    flash_kernel<<<dim3(16, Hn, Bn), 256, FLASH_SMEM>>>(qkv, o);
    // 5. proj + bias + residual(x1): x2 = x1 + o@Wp + bp
    sgemm_kernel<true, true, false><<<dim3(8, 64), 256>>>(o, Wp, bp, x1, x2, Mn, Cn, Cn);
    // 6. LN2
    ln_kernel<<<Mn, 256>>>(x2, g2, be2, x3);
    // 7. FFN up + relu: hb = relu(x3@W1 + b1)   [8192,1024]@[1024,4096]
    sgemm_kernel<true, false, true><<<dim3(32, 64), 256>>>(x3, W1, b1, nullptr, hb, Mn, FFn, Cn);
    // 8. FFN down + bias + residual(x3): out = x3 + hb@W2 + b2   [8192,4096]@[4096,1024]
    sgemm_kernel<true, true, false><<<dim3(8, 64), 256>>>(hb, W2, b2, x3, out, Mn, Cn, FFn);
}

// round 6
// speedup vs baseline: 1.0786x; 1.0786x over previous
#include <cuda_runtime.h>
#include <math.h>
#include <stdint.h>

// Problem constants
#define Bn 4
#define Tn 2048
#define Cn 1024
#define Hn 16
#define HSn 64
#define Mn (Bn * Tn)        // 8192 rows
#define FFn (4 * Cn)        // 4096

// ---------------------------------------------------------------------------
// Scratch (device globals -- no allocation allowed in kernel_launch)
// ---------------------------------------------------------------------------
__device__ float g_x1[8388608];    // [M, C]  LN1 output
__device__ float g_qkv[25165824];  // [M, 3C] q|k|v, col = which*1024 + h*64 + d
__device__ float g_o[8388608];     // [M, C]  attention output (head-concat)
__device__ float g_x2[8388608];    // [M, C]  x1 + o@Wp + bp
__device__ float g_x3[8388608];    // [M, C]  LN2 output
__device__ float g_hb[33554432];   // [M, 4C] relu(x3@W1+b1)
__device__ float g_wqkv[3145728];  // [C, 3C] packed Wq|Wk|Wv

// ---------------------------------------------------------------------------
// LayerNorm: one block per row (C=1024, 256 threads x float4)
// ---------------------------------------------------------------------------
__global__ void ln_kernel(const float* __restrict__ x, const float* __restrict__ g,
                          const float* __restrict__ beta, float* __restrict__ y)
{
    const int row = blockIdx.x;
    const int t = threadIdx.x;
    const float4 v = reinterpret_cast<const float4*>(x + (size_t)row * Cn)[t];
    float s = v.x + v.y + v.z + v.w;
    float q = v.x * v.x + v.y * v.y + v.z * v.z + v.w * v.w;
#pragma unroll
    for (int off = 16; off; off >>= 1) {
        s += __shfl_xor_sync(0xffffffffu, s, off);
        q += __shfl_xor_sync(0xffffffffu, q, off);
    }
    __shared__ float ss[8], qs[8];
    if ((t & 31) == 0) { ss[t >> 5] = s; qs[t >> 5] = q; }
    __syncthreads();
    s = 0.f; q = 0.f;
#pragma unroll
    for (int i = 0; i < 8; i++) { s += ss[i]; q += qs[i]; }
    const float mu = s * (1.0f / Cn);
    const float var = q * (1.0f / Cn) - mu * mu;
    const float rstd = rsqrtf(var + 1e-5f);
    const float4 gv = reinterpret_cast<const float4*>(g)[t];
    const float4 bv = reinterpret_cast<const float4*>(beta)[t];
    float4 o;
    o.x = (v.x - mu) * rstd * gv.x + bv.x;
    o.y = (v.y - mu) * rstd * gv.y + bv.y;
    o.z = (v.z - mu) * rstd * gv.z + bv.z;
    o.w = (v.w - mu) * rstd * gv.w + bv.w;
    reinterpret_cast<float4*>(y + (size_t)row * Cn)[t] = o;
}

// ---------------------------------------------------------------------------
// Pack Wq/Wk/Wv ([H,C,HS] each) into one [C, 3C] GEMM-friendly matrix.
// ---------------------------------------------------------------------------
__global__ void pack_wqkv_kernel(const float* __restrict__ Wq, const float* __restrict__ Wk,
                                 const float* __restrict__ Wv, float* __restrict__ out)
{
    const int k = blockIdx.y;                       // 0..1023
    const int j = blockIdx.x * 256 + threadIdx.x;   // 0..3071
    const int which = j >> 10;
    const int jj = j & 1023;
    const int h = jj >> 6, d = jj & 63;
    const float* W = (which == 0) ? Wq : (which == 1) ? Wk : Wv;
    out[(size_t)k * 3072 + j] = W[((size_t)h * Cn + k) * HSn + d];
}

// ---------------------------------------------------------------------------
// Tensor-core tf32 GEMM: C[M,N] = A[M,K] @ B[K,N] (+bias)(+res)(relu)
// 128x128x32 block tile, 8 warps (2x4), 64x32 warp tile,
// mma.sync.m16n8k8.tf32, permuted smem so fragment loads are LDS.128/LDS.64.
// Requires M%128==0, N%128==0, K%32==0.
// ---------------------------------------------------------------------------
__device__ __forceinline__ uint32_t f2tf(float f)
{
    uint32_t u;
    asm("cvt.rna.tf32.f32 %0, %1;" : "=r"(u) : "f"(f));
    return u;
}

template <bool BIAS, bool RES, bool RELU>
__global__ __launch_bounds__(256) void tgemm_kernel(
    const float* __restrict__ A, const float* __restrict__ Bm,
    const float* __restrict__ bias, const float* __restrict__ res,
    float* __restrict__ C, int Mdim, int Ndim, int Kdim)
{
    extern __shared__ uint32_t smem_u[];
    // As: [2][4096] u32 permuted A tile (128x32), Bs: [2][4096] permuted B tile (32x128)
    uint32_t* AsBase = smem_u;
    uint32_t* BsBase = smem_u + 8192;

    const int tid = threadIdx.x;
    const int lane = tid & 31;
    const int wid = tid >> 5;
    const int warp_m = wid >> 2;   // 0..1   (64 rows each)
    const int warp_n = wid & 3;    // 0..3   (32 cols each)
    const int m0 = blockIdx.y * 128;
    const int n0 = blockIdx.x * 128;

    const float* Ag = A + (size_t)m0 * Kdim;
    const float* Bg = Bm + n0;

    // ---- per-thread global-load / smem-scatter precompute ----
    // A tile: 128 rows x 32 cols = 1024 float4 slots; B tile: 32 x 128 same.
    int am[4], akq[4], baseA[4];
    int bk[4], bnq[4], baseB[4];
#pragma unroll
    for (int i = 0; i < 4; i++) {
        const int slot = tid + 256 * i;
        // A: m = slot>>3, k-quad = slot&7
        const int m = slot >> 3, kq = slot & 7;
        am[i] = m; akq[i] = kq;
        const int mt = m >> 4, mlo = m & 15, rh = mlo >> 3, r = mlo & 7;
        baseA[i] = ((mt * 4 + (kq >> 1)) * 32 + r * 4) * 4 + (kq & 1) * 2 + rh;
        // B: k = slot>>5, n-quad = slot&31
        const int k = slot >> 5, nq = slot & 31;
        bk[i] = k; bnq[i] = nq;
        const int kt = k >> 3, kc = k & 7, kh = kc >> 2, klo = kc & 3;
        baseB[i] = (((nq >> 1) * 4 + kt) * 32 + (nq & 1) * 16 + klo) * 2 + kh;
    }

    float4 av[4], bv[4];
    auto gload = [&](int kt) {
#pragma unroll
        for (int i = 0; i < 4; i++)
            av[i] = *reinterpret_cast<const float4*>(Ag + (size_t)am[i] * Kdim + kt * 32 + akq[i] * 4);
#pragma unroll
        for (int i = 0; i < 4; i++)
            bv[i] = *reinterpret_cast<const float4*>(Bg + (size_t)(kt * 32 + bk[i]) * Ndim + bnq[i] * 4);
    };
    auto sstore = [&](int buf) {
        uint32_t* As = AsBase + buf * 4096;
        uint32_t* Bs = BsBase + buf * 4096;
#pragma unroll
        for (int i = 0; i < 4; i++) {
            As[baseA[i] + 0]  = f2tf(av[i].x);
            As[baseA[i] + 4]  = f2tf(av[i].y);
            As[baseA[i] + 8]  = f2tf(av[i].z);
            As[baseA[i] + 12] = f2tf(av[i].w);
        }
#pragma unroll
        for (int i = 0; i < 4; i++) {
            Bs[baseB[i] + 0]  = f2tf(bv[i].x);
            Bs[baseB[i] + 8]  = f2tf(bv[i].y);
            Bs[baseB[i] + 16] = f2tf(bv[i].z);
            Bs[baseB[i] + 24] = f2tf(bv[i].w);
        }
    };

    float acc[4][4][4];
#pragma unroll
    for (int i = 0; i < 4; i++)
#pragma unroll
        for (int j = 0; j < 4; j++)
#pragma unroll
            for (int r = 0; r < 4; r++) acc[i][j][r] = 0.f;

    gload(0);
    sstore(0);
    __syncthreads();

    const int nk = Kdim / 32;
    int buf = 0;
    for (int kt = 0; kt < nk; kt++) {
        if (kt + 1 < nk) gload(kt + 1);

        const uint4* As4 = reinterpret_cast<const uint4*>(AsBase + buf * 4096);
        const uint2* Bs2 = reinterpret_cast<const uint2*>(BsBase + buf * 4096);
#pragma unroll
        for (int ks = 0; ks < 4; ks++) {
            uint4 af[4];
            uint2 bf[4];
#pragma unroll
            for (int i = 0; i < 4; i++)
                af[i] = As4[((warp_m * 4 + i) * 4 + ks) * 32 + lane];
#pragma unroll
            for (int j = 0; j < 4; j++)
                bf[j] = Bs2[((warp_n * 4 + j) * 4 + ks) * 32 + lane];
#pragma unroll
            for (int i = 0; i < 4; i++)
#pragma unroll
                for (int j = 0; j < 4; j++) {
                    asm volatile(
                        "mma.sync.aligned.m16n8k8.row.col.f32.tf32.tf32.f32 "
                        "{%0,%1,%2,%3}, {%4,%5,%6,%7}, {%8,%9}, {%0,%1,%2,%3};\n"
                        : "+f"(acc[i][j][0]), "+f"(acc[i][j][1]),
                          "+f"(acc[i][j][2]), "+f"(acc[i][j][3])
                        : "r"(af[i].x), "r"(af[i].y), "r"(af[i].z), "r"(af[i].w),
                          "r"(bf[j].x), "r"(bf[j].y));
                }
        }

        if (kt + 1 < nk) {
            sstore(buf ^ 1);
            __syncthreads();
            buf ^= 1;
        }
    }

    // ---- epilogue ----
    const int g = lane >> 2, tg = lane & 3;
#pragma unroll
    for (int i = 0; i < 4; i++) {
#pragma unroll
        for (int j = 0; j < 4; j++) {
            const int col = n0 + warp_n * 32 + j * 8 + tg * 2;
            float2 bb = {0.f, 0.f};
            if (BIAS) bb = *reinterpret_cast<const float2*>(bias + col);
#pragma unroll
            for (int half = 0; half < 2; half++) {
                const int row = m0 + warp_m * 64 + i * 16 + g + half * 8;
                float2 v;
                v.x = acc[i][j][half * 2 + 0];
                v.y = acc[i][j][half * 2 + 1];
                if (BIAS) { v.x += bb.x; v.y += bb.y; }
                if (RES) {
                    const float2 rr = *reinterpret_cast<const float2*>(res + (size_t)row * Ndim + col);
                    v.x += rr.x; v.y += rr.y;
                }
                if (RELU) { v.x = fmaxf(v.x, 0.f); v.y = fmaxf(v.y, 0.f); }
                *reinterpret_cast<float2*>(C + (size_t)row * Ndim + col) = v;
            }
        }
    }
}

// ---------------------------------------------------------------------------
// Causal flash attention (fp32). One block per (query-tile of 128, head, batch).
// ---------------------------------------------------------------------------
__global__ __launch_bounds__(256, 2) void flash_kernel(const float* __restrict__ qkv,
                                                       float* __restrict__ o)
{
    extern __shared__ float sm_f[];
    float* Qt = sm_f;                // [64][128]  Qt[d*128 + r]
    float* Kt = Qt + 64 * 128;       // [64][64]   Kt[d*64  + c]
    float* Vs = Kt + 64 * 64;        // [64][64]   Vs[k*64  + d]
    float* Ps = Vs + 64 * 64;        // [128][68]  Ps[r*68  + k] (padded)

    const int t  = threadIdx.x;
    const int tx = t & 15, ty = t >> 4;
    const int qi = (int)gridDim.x - 1 - (int)blockIdx.x;  // big tiles first
    const int h  = blockIdx.y, b = blockIdx.z;
    const int q0 = qi * 128;

    const float* Qg = qkv + ((size_t)(b * Tn + q0)) * 3072 + h * 64;
    const float* Kg = qkv + ((size_t)(b * Tn)) * 3072 + 1024 + h * 64;
    const float* Vg = Kg + 1024;

#pragma unroll
    for (int u = 0; u < 8; u++) {
        const int f = t + 256 * u;
        const int r = f >> 4, d = (f & 15) << 2;
        const float4 v = *reinterpret_cast<const float4*>(Qg + (size_t)r * 3072 + d);
        Qt[(d + 0) * 128 + r] = v.x;
        Qt[(d + 1) * 128 + r] = v.y;
        Qt[(d + 2) * 128 + r] = v.z;
        Qt[(d + 3) * 128 + r] = v.w;
    }

    float oacc[8][4];
    float m[8], l[8];
#pragma unroll
    for (int i = 0; i < 8; i++) {
        m[i] = -1e30f; l[i] = 0.f;
#pragma unroll
        for (int j = 0; j < 4; j++) oacc[i][j] = 0.f;
    }

    const int ntiles = 2 * qi + 2;
    for (int jt = 0; jt < ntiles; jt++) {
        const int j0 = jt * 64;
        __syncthreads();
#pragma unroll
        for (int u = 0; u < 4; u++) {
            const int f = t + 256 * u;
            const int c = f >> 4, d = (f & 15) << 2;
            const float4 kv = *reinterpret_cast<const float4*>(Kg + (size_t)(j0 + c) * 3072 + d);
            Kt[(d + 0) * 64 + c] = kv.x;
            Kt[(d + 1) * 64 + c] = kv.y;
            Kt[(d + 2) * 64 + c] = kv.z;
            Kt[(d + 3) * 64 + c] = kv.w;
            const float4 vv = *reinterpret_cast<const float4*>(Vg + (size_t)(j0 + c) * 3072 + d);
            *reinterpret_cast<float4*>(Vs + c * 64 + d) = vv;
        }
        __syncthreads();

        float s[8][4];
#pragma unroll
        for (int i = 0; i < 8; i++)
#pragma unroll
            for (int j = 0; j < 4; j++) s[i][j] = 0.f;

#pragma unroll 4
        for (int d = 0; d < 64; d++) {
            const float4 a0 = *reinterpret_cast<const float4*>(Qt + d * 128 + ty * 8);
            const float4 a1 = *reinterpret_cast<const float4*>(Qt + d * 128 + ty * 8 + 4);
            const float4 bb = *reinterpret_cast<const float4*>(Kt + d * 64 + tx * 4);
            const float av[8] = {a0.x, a0.y, a0.z, a0.w, a1.x, a1.y, a1.z, a1.w};
            const float bw[4] = {bb.x, bb.y, bb.z, bb.w};
#pragma unroll
            for (int i = 0; i < 8; i++)
#pragma unroll
                for (int j = 0; j < 4; j++) s[i][j] += av[i] * bw[j];
        }

#pragma unroll
        for (int i = 0; i < 8; i++) {
            const int q = q0 + ty * 8 + i;
#pragma unroll
            for (int j = 0; j < 4; j++) {
                const int key = j0 + tx * 4 + j;
                s[i][j] = (key <= q) ? s[i][j] * 0.03125f : -1e30f;
            }
        }

#pragma unroll
        for (int i = 0; i < 8; i++) {
            float mt = fmaxf(fmaxf(s[i][0], s[i][1]), fmaxf(s[i][2], s[i][3]));
#pragma unroll
            for (int off = 8; off; off >>= 1)
                mt = fmaxf(mt, __shfl_xor_sync(0xffffffffu, mt, off));
            const float mn = fmaxf(m[i], mt);
            const float corr = __expf(m[i] - mn);
            float rs = 0.f;
#pragma unroll
            for (int j = 0; j < 4; j++) {
                const float p = __expf(s[i][j] - mn);
                s[i][j] = p; rs += p;
            }
#pragma unroll
            for (int off = 8; off; off >>= 1)
                rs += __shfl_xor_sync(0xffffffffu, rs, off);
            l[i] = l[i] * corr + rs;
            m[i] = mn;
#pragma unroll
            for (int j = 0; j < 4; j++) oacc[i][j] *= corr;
        }

#pragma unroll
        for (int i = 0; i < 8; i++)
#pragma unroll
            for (int j = 0; j < 4; j++)
                Ps[(ty * 8 + i) * 68 + tx * 4 + j] = s[i][j];
        __syncthreads();

#pragma unroll 4
        for (int k = 0; k < 64; k++) {
            const float4 vv = *reinterpret_cast<const float4*>(Vs + k * 64 + tx * 4);
            const float bw[4] = {vv.x, vv.y, vv.z, vv.w};
            float av[8];
#pragma unroll
            for (int i = 0; i < 8; i++) av[i] = Ps[(ty * 8 + i) * 68 + k];
#pragma unroll
            for (int i = 0; i < 8; i++)
#pragma unroll
                for (int j = 0; j < 4; j++) oacc[i][j] += av[i] * bw[j];
        }
    }

    float* Og = o + ((size_t)(b * Tn + q0)) * Cn + h * 64;
#pragma unroll
    for (int i = 0; i < 8; i++) {
        const float inv = 1.0f / l[i];
        const int r = ty * 8 + i;
        float4 v;
        v.x = oacc[i][0] * inv; v.y = oacc[i][1] * inv;
        v.z = oacc[i][2] * inv; v.w = oacc[i][3] * inv;
        *reinterpret_cast<float4*>(Og + (size_t)r * Cn + tx * 4) = v;
    }
}

// ---------------------------------------------------------------------------
// Launch sequence
// ---------------------------------------------------------------------------
extern "C" void kernel_launch(void* const* d_in, const int* in_sizes, int n_in,
                              void* d_out, int out_size)
{
    const float* x   = (const float*)d_in[0];
    const float* Wq  = (const float*)d_in[1];
    const float* Wk  = (const float*)d_in[2];
    const float* Wv  = (const float*)d_in[3];
    const float* Wp  = (const float*)d_in[4];
    const float* bp  = (const float*)d_in[5];
    const float* W1  = (const float*)d_in[6];
    const float* b1  = (const float*)d_in[7];
    const float* W2  = (const float*)d_in[8];
    const float* b2  = (const float*)d_in[9];
    const float* g1  = (const float*)d_in[10];
    const float* be1 = (const float*)d_in[11];
    const float* g2  = (const float*)d_in[12];
    const float* be2 = (const float*)d_in[13];
    float* out = (float*)d_out;

    float *x1, *qkv, *o, *x2, *x3, *hb, *wqkv;
    cudaGetSymbolAddress((void**)&x1,   g_x1);
    cudaGetSymbolAddress((void**)&qkv,  g_qkv);
    cudaGetSymbolAddress((void**)&o,    g_o);
    cudaGetSymbolAddress((void**)&x2,   g_x2);
    cudaGetSymbolAddress((void**)&x3,   g_x3);
    cudaGetSymbolAddress((void**)&hb,   g_hb);
    cudaGetSymbolAddress((void**)&wqkv, g_wqkv);

    constexpr int GEMM_SMEM = 16384 * 4;  // 64 KB (2 bufs x (A 16KB + B 16KB))
    cudaFuncSetAttribute(tgemm_kernel<false, false, false>, cudaFuncAttributeMaxDynamicSharedMemorySize, GEMM_SMEM);
    cudaFuncSetAttribute(tgemm_kernel<true,  true,  false>, cudaFuncAttributeMaxDynamicSharedMemorySize, GEMM_SMEM);
    cudaFuncSetAttribute(tgemm_kernel<true,  false, true >, cudaFuncAttributeMaxDynamicSharedMemorySize, GEMM_SMEM);

    constexpr int FLASH_SMEM = (64 * 128 + 64 * 64 + 64 * 64 + 128 * 68) * 4; // 100352 B
    cudaFuncSetAttribute(flash_kernel, cudaFuncAttributeMaxDynamicSharedMemorySize, FLASH_SMEM);

    // 1. LN1
    ln_kernel<<<Mn, 256>>>(x, g1, be1, x1);
    // 2. pack QKV weights
    pack_wqkv_kernel<<<dim3(12, 1024), 256>>>(Wq, Wk, Wv, wqkv);
    // 3. QKV GEMM: [8192,1024] @ [1024,3072]
    tgemm_kernel<false, false, false><<<dim3(24, 64), 256, GEMM_SMEM>>>(x1, wqkv, nullptr, nullptr, qkv, Mn, 3 * Cn, Cn);
    // 4. causal flash attention
    flash_kernel<<<dim3(16, Hn, Bn), 256, FLASH_SMEM>>>(qkv, o);
    // 5. proj + bias + residual(x1): x2 = x1 + o@Wp + bp
    tgemm_kernel<true, true, false><<<dim3(8, 64), 256, GEMM_SMEM>>>(o, Wp, bp, x1, x2, Mn, Cn, Cn);
    // 6. LN2
    ln_kernel<<<Mn, 256>>>(x2, g2, be2, x3);
    // 7. FFN up + relu: hb = relu(x3@W1 + b1)
    tgemm_kernel<true, false, true><<<dim3(32, 64), 256, GEMM_SMEM>>>(x3, W1, b1, nullptr, hb, Mn, FFn, Cn);
    // 8. FFN down + bias + residual(x3): out = x3 + hb@W2 + b2
    tgemm_kernel<true, true, false><<<dim3(8, 64), 256, GEMM_SMEM>>>(hb, W2, b2, x3, out, Mn, Cn, FFn);
}

// round 8
// speedup vs baseline: 3.0275x; 2.8068x over previous
#include <cuda_runtime.h>
#include <cuda_fp16.h>
#include <math.h>
#include <stdint.h>

// Problem constants
#define Bn 4
#define Tn 2048
#define Cn 1024
#define Hn 16
#define HSn 64
#define Mn (Bn * Tn)        // 8192 rows
#define FFn (4 * Cn)        // 4096

// ---------------------------------------------------------------------------
// Scratch (device globals -- no allocation allowed in kernel_launch)
// ---------------------------------------------------------------------------
__device__ float  g_x1 [8388608];     // [M, C]  LN1 output (f32, residual use)
__device__ float  g_qkv[25165824];    // [M, 3C] q|k|v (f32, flash input)
__device__ float  g_x2 [8388608];     // [M, C]
__device__ float  g_x3 [8388608];     // [M, C]
__device__ __half g_x1h[8388608];     // [M, C]  LN1 output (f16, GEMM input)
__device__ __half g_x3h[8388608];     // [M, C]  LN2 output (f16, GEMM input)
__device__ __half g_oh [8388608];     // [M, C]  attention out (f16)
__device__ __half g_hbh[33554432];    // [M, 4C] relu FFN intermediate (f16)
__device__ __half g_wqkvT[3145728];   // [3C, C] packed+transposed Wq|Wk|Wv (f16 [N][K])
__device__ __half g_wpT[1048576];     // [C, C]   Wp^T  (f16 [N][K])
__device__ __half g_w1T[4194304];     // [4C, C]  W1^T  (f16 [N][K])
__device__ __half g_w2T[4194304];     // [C, 4C]  W2^T  (f16 [N][K])

// ---------------------------------------------------------------------------
// LayerNorm (dual output: f32 + f16): one block per row
// ---------------------------------------------------------------------------
__global__ void ln_kernel(const float* __restrict__ x, const float* __restrict__ g,
                          const float* __restrict__ beta, float* __restrict__ y,
                          __half* __restrict__ yh)
{
    const int row = blockIdx.x;
    const int t = threadIdx.x;
    const float4 v = reinterpret_cast<const float4*>(x + (size_t)row * Cn)[t];
    float s = v.x + v.y + v.z + v.w;
    float q = v.x * v.x + v.y * v.y + v.z * v.z + v.w * v.w;
#pragma unroll
    for (int off = 16; off; off >>= 1) {
        s += __shfl_xor_sync(0xffffffffu, s, off);
        q += __shfl_xor_sync(0xffffffffu, q, off);
    }
    __shared__ float ss[8], qs[8];
    if ((t & 31) == 0) { ss[t >> 5] = s; qs[t >> 5] = q; }
    __syncthreads();
    s = 0.f; q = 0.f;
#pragma unroll
    for (int i = 0; i < 8; i++) { s += ss[i]; q += qs[i]; }
    const float mu = s * (1.0f / Cn);
    const float var = q * (1.0f / Cn) - mu * mu;
    const float rstd = rsqrtf(var + 1e-5f);
    const float4 gv = reinterpret_cast<const float4*>(g)[t];
    const float4 bv = reinterpret_cast<const float4*>(beta)[t];
    float4 o;
    o.x = (v.x - mu) * rstd * gv.x + bv.x;
    o.y = (v.y - mu) * rstd * gv.y + bv.y;
    o.z = (v.z - mu) * rstd * gv.z + bv.z;
    o.w = (v.w - mu) * rstd * gv.w + bv.w;
    reinterpret_cast<float4*>(y + (size_t)row * Cn)[t] = o;
    __half2* hp = reinterpret_cast<__half2*>(yh + (size_t)row * Cn + t * 4);
    hp[0] = __floats2half2_rn(o.x, o.y);
    hp[1] = __floats2half2_rn(o.z, o.w);
}

// ---------------------------------------------------------------------------
// Pack Wq/Wk/Wv ([H,C,HS] each) into one TRANSPOSED fp16 [3C][C] matrix.
// ---------------------------------------------------------------------------
__global__ void pack_wqkvT_kernel(const float* __restrict__ Wq, const float* __restrict__ Wk,
                                  const float* __restrict__ Wv, __half* __restrict__ out)
{
    const int n = blockIdx.y;                        // 0..3071
    const int k = blockIdx.x * 256 + threadIdx.x;    // 0..1023
    const int which = n >> 10;
    const int jj = n & 1023;
    const int h = jj >> 6, d = jj & 63;
    const float* W = (which == 0) ? Wq : (which == 1) ? Wk : Wv;
    out[(size_t)n * Cn + k] = __float2half(W[((size_t)h * Cn + k) * HSn + d]);
}

// ---------------------------------------------------------------------------
// Tiled transpose to fp16: out[Cc][R] = half(in[R][Cc]^T)
// ---------------------------------------------------------------------------
__global__ void transpose_kernel(const float* __restrict__ in, __half* __restrict__ out,
                                 int R, int Cc)
{
    __shared__ float t[32][33];
    const int c0 = blockIdx.x * 32, r0 = blockIdx.y * 32;
    const int x = threadIdx.x, y = threadIdx.y;
#pragma unroll
    for (int i = 0; i < 32; i += 8)
        t[y + i][x] = in[(size_t)(r0 + y + i) * Cc + c0 + x];
    __syncthreads();
#pragma unroll
    for (int i = 0; i < 32; i += 8)
        out[(size_t)(c0 + y + i) * R + r0 + x] = __float2half(t[x][y + i]);
}

// ---------------------------------------------------------------------------
// fp16 tensor-core GEMM: C[M,N] = A[M,K] @ Bt[N,K]^T (+bias)(+res)(relu)
// A, Bt fp16; accumulate fp32. 128x128x32 block tile, 8 warps (2x4),
// warp tile 64x32, mma.sync.m16n8k16. Smem rows padded to 40 halfs (80B,
// 5*16B -> conflict-free 32-bit fragment loads). Double-buffered.
// Requires M%128==0, N%128==0, K%32==0.
// ---------------------------------------------------------------------------
template <bool BIAS, bool RES, bool RELU, bool OUTH>
__global__ __launch_bounds__(256) void hgemm_kernel(
    const __half* __restrict__ A, const __half* __restrict__ Bt,
    const float* __restrict__ bias, const float* __restrict__ res,
    float* __restrict__ C, __half* __restrict__ Ch,
    int Mdim, int Ndim, int Kdim)
{
    extern __shared__ __half sm_h[];
    // layout (halfs): A buf0 [128*40], A buf1, B buf0, B buf1
    __half* Abuf = sm_h;
    __half* Bbuf = sm_h + 2 * 5120;

    const int tid  = threadIdx.x;
    const int lane = tid & 31;
    const int wid  = tid >> 5;
    const int warp_m = wid >> 2;   // 0..1 (64 rows)
    const int warp_n = wid & 3;    // 0..3 (32 cols)
    const int m0 = blockIdx.y * 128;
    const int n0 = blockIdx.x * 128;

    // global<->smem mapping: slot covers one 16B chunk (8 halfs) of a 32-half row
    const int r0c = tid >> 2;          // rows 0..63 (slot0), +64 (slot1)
    const int ch  = (tid & 3) * 8;     // half offset within row: 0,8,16,24

    const __half* Ag = A  + (size_t)m0 * Kdim;
    const __half* Bg = Bt + (size_t)n0 * Kdim;

    uint4 ra0, ra1, rb0, rb1;
    auto gload = [&](int kt) {
        const int kb = kt * 32 + ch;
        ra0 = *reinterpret_cast<const uint4*>(Ag + (size_t)(r0c)      * Kdim + kb);
        ra1 = *reinterpret_cast<const uint4*>(Ag + (size_t)(r0c + 64) * Kdim + kb);
        rb0 = *reinterpret_cast<const uint4*>(Bg + (size_t)(r0c)      * Kdim + kb);
        rb1 = *reinterpret_cast<const uint4*>(Bg + (size_t)(r0c + 64) * Kdim + kb);
    };
    auto sstore = [&](int buf) {
        __half* Ab = Abuf + buf * 5120;
        __half* Bb = Bbuf + buf * 5120;
        *reinterpret_cast<uint4*>(Ab + (r0c)      * 40 + ch) = ra0;
        *reinterpret_cast<uint4*>(Ab + (r0c + 64) * 40 + ch) = ra1;
        *reinterpret_cast<uint4*>(Bb + (r0c)      * 40 + ch) = rb0;
        *reinterpret_cast<uint4*>(Bb + (r0c + 64) * 40 + ch) = rb1;
    };

    float acc[4][4][4];
#pragma unroll
    for (int i = 0; i < 4; i++)
#pragma unroll
        for (int j = 0; j < 4; j++)
#pragma unroll
            for (int r = 0; r < 4; r++) acc[i][j][r] = 0.f;

    gload(0);
    sstore(0);
    __syncthreads();

    const int g  = lane >> 2;    // 0..7
    const int t4 = lane & 3;     // 0..3
    const int nk = Kdim / 32;
    int buf = 0;

    for (int kt = 0; kt < nk; kt++) {
        if (kt + 1 < nk) gload(kt + 1);

        const __half* As = Abuf + buf * 5120;
        const __half* Bs = Bbuf + buf * 5120;
#pragma unroll
        for (int ks = 0; ks < 2; ks++) {
            const int kb = ks * 16 + t4 * 2;
            uint32_t a[4][4], b[4][2];
#pragma unroll
            for (int i = 0; i < 4; i++) {
                const int rA = warp_m * 64 + i * 16 + g;
                a[i][0] = *reinterpret_cast<const uint32_t*>(As + (rA)     * 40 + kb);
                a[i][1] = *reinterpret_cast<const uint32_t*>(As + (rA + 8) * 40 + kb);
                a[i][2] = *reinterpret_cast<const uint32_t*>(As + (rA)     * 40 + kb + 8);
                a[i][3] = *reinterpret_cast<const uint32_t*>(As + (rA + 8) * 40 + kb + 8);
            }
#pragma unroll
            for (int j = 0; j < 4; j++) {
                const int nB = warp_n * 32 + j * 8 + g;
                b[j][0] = *reinterpret_cast<const uint32_t*>(Bs + nB * 40 + kb);
                b[j][1] = *reinterpret_cast<const uint32_t*>(Bs + nB * 40 + kb + 8);
            }
#pragma unroll
            for (int i = 0; i < 4; i++)
#pragma unroll
                for (int j = 0; j < 4; j++) {
                    asm volatile(
                        "mma.sync.aligned.m16n8k16.row.col.f32.f16.f16.f32 "
                        "{%0,%1,%2,%3}, {%4,%5,%6,%7}, {%8,%9}, {%0,%1,%2,%3};\n"
                        : "+f"(acc[i][j][0]), "+f"(acc[i][j][1]),
                          "+f"(acc[i][j][2]), "+f"(acc[i][j][3])
                        : "r"(a[i][0]), "r"(a[i][1]), "r"(a[i][2]), "r"(a[i][3]),
                          "r"(b[j][0]), "r"(b[j][1]));
                }
        }

        if (kt + 1 < nk) {
            sstore(buf ^ 1);
            __syncthreads();
            buf ^= 1;
        }
    }

    // ---- epilogue (m16n8 acc layout) ----
#pragma unroll
    for (int i = 0; i < 4; i++) {
#pragma unroll
        for (int j = 0; j < 4; j++) {
            const int col = n0 + warp_n * 32 + j * 8 + t4 * 2;
            float2 bb = {0.f, 0.f};
            if (BIAS) bb = *reinterpret_cast<const float2*>(bias + col);
#pragma unroll
            for (int half = 0; half < 2; half++) {
                const int row = m0 + warp_m * 64 + i * 16 + g + half * 8;
                float2 v;
                v.x = acc[i][j][half * 2 + 0];
                v.y = acc[i][j][half * 2 + 1];
                if (BIAS) { v.x += bb.x; v.y += bb.y; }
                if (RES) {
                    const float2 rr = *reinterpret_cast<const float2*>(res + (size_t)row * Ndim + col);
                    v.x += rr.x; v.y += rr.y;
                }
                if (RELU) { v.x = fmaxf(v.x, 0.f); v.y = fmaxf(v.y, 0.f); }
                if (OUTH) {
                    *reinterpret_cast<__half2*>(Ch + (size_t)row * Ndim + col) =
                        __floats2half2_rn(v.x, v.y);
                } else {
                    *reinterpret_cast<float2*>(C + (size_t)row * Ndim + col) = v;
                }
            }
        }
    }
}

// ---------------------------------------------------------------------------
// Causal flash attention (fp32 compute, fp16 output).
// One block per (query-tile of 128, head, batch).
// ---------------------------------------------------------------------------
__global__ __launch_bounds__(256, 2) void flash_kernel(const float* __restrict__ qkv,
                                                       __half* __restrict__ o)
{
    extern __shared__ float sm_f[];
    float* Qt = sm_f;                // [64][128]
    float* Kt = Qt + 64 * 128;       // [64][64]
    float* Vs = Kt + 64 * 64;        // [64][64]
    float* Ps = Vs + 64 * 64;        // [128][68]

    const int t  = threadIdx.x;
    const int tx = t & 15, ty = t >> 4;
    const int qi = (int)gridDim.x - 1 - (int)blockIdx.x;
    const int h  = blockIdx.y, b = blockIdx.z;
    const int q0 = qi * 128;

    const float* Qg = qkv + ((size_t)(b * Tn + q0)) * 3072 + h * 64;
    const float* Kg = qkv + ((size_t)(b * Tn)) * 3072 + 1024 + h * 64;
    const float* Vg = Kg + 1024;

#pragma unroll
    for (int u = 0; u < 8; u++) {
        const int f = t + 256 * u;
        const int r = f >> 4, d = (f & 15) << 2;
        const float4 v = *reinterpret_cast<const float4*>(Qg + (size_t)r * 3072 + d);
        Qt[(d + 0) * 128 + r] = v.x;
        Qt[(d + 1) * 128 + r] = v.y;
        Qt[(d + 2) * 128 + r] = v.z;
        Qt[(d + 3) * 128 + r] = v.w;
    }

    float oacc[8][4];
    float m[8], l[8];
#pragma unroll
    for (int i = 0; i < 8; i++) {
        m[i] = -1e30f; l[i] = 0.f;
#pragma unroll
        for (int j = 0; j < 4; j++) oacc[i][j] = 0.f;
    }

    const int ntiles = 2 * qi + 2;
    for (int jt = 0; jt < ntiles; jt++) {
        const int j0 = jt * 64;
        __syncthreads();
#pragma unroll
        for (int u = 0; u < 4; u++) {
            const int f = t + 256 * u;
            const int c = f >> 4, d = (f & 15) << 2;
            const float4 kv = *reinterpret_cast<const float4*>(Kg + (size_t)(j0 + c) * 3072 + d);
            Kt[(d + 0) * 64 + c] = kv.x;
            Kt[(d + 1) * 64 + c] = kv.y;
            Kt[(d + 2) * 64 + c] = kv.z;
            Kt[(d + 3) * 64 + c] = kv.w;
            const float4 vv = *reinterpret_cast<const float4*>(Vg + (size_t)(j0 + c) * 3072 + d);
            *reinterpret_cast<float4*>(Vs + c * 64 + d) = vv;
        }
        __syncthreads();

        float s[8][4];
#pragma unroll
        for (int i = 0; i < 8; i++)
#pragma unroll
            for (int j = 0; j < 4; j++) s[i][j] = 0.f;

#pragma unroll 4
        for (int d = 0; d < 64; d++) {
            const float4 a0 = *reinterpret_cast<const float4*>(Qt + d * 128 + ty * 8);
            const float4 a1 = *reinterpret_cast<const float4*>(Qt + d * 128 + ty * 8 + 4);
            const float4 bb = *reinterpret_cast<const float4*>(Kt + d * 64 + tx * 4);
            const float av[8] = {a0.x, a0.y, a0.z, a0.w, a1.x, a1.y, a1.z, a1.w};
            const float bw[4] = {bb.x, bb.y, bb.z, bb.w};
#pragma unroll
            for (int i = 0; i < 8; i++)
#pragma unroll
                for (int j = 0; j < 4; j++) s[i][j] += av[i] * bw[j];
        }

#pragma unroll
        for (int i = 0; i < 8; i++) {
            const int q = q0 + ty * 8 + i;
#pragma unroll
            for (int j = 0; j < 4; j++) {
                const int key = j0 + tx * 4 + j;
                s[i][j] = (key <= q) ? s[i][j] * 0.03125f : -1e30f;
            }
        }

#pragma unroll
        for (int i = 0; i < 8; i++) {
            float mt = fmaxf(fmaxf(s[i][0], s[i][1]), fmaxf(s[i][2], s[i][3]));
#pragma unroll
            for (int off = 8; off; off >>= 1)
                mt = fmaxf(mt, __shfl_xor_sync(0xffffffffu, mt, off));
            const float mn = fmaxf(m[i], mt);
            const float corr = __expf(m[i] - mn);
            float rs = 0.f;
#pragma unroll
            for (int j = 0; j < 4; j++) {
                const float p = __expf(s[i][j] - mn);
                s[i][j] = p; rs += p;
            }
#pragma unroll
            for (int off = 8; off; off >>= 1)
                rs += __shfl_xor_sync(0xffffffffu, rs, off);
            l[i] = l[i] * corr + rs;
            m[i] = mn;
#pragma unroll
            for (int j = 0; j < 4; j++) oacc[i][j] *= corr;
        }

#pragma unroll
        for (int i = 0; i < 8; i++)
#pragma unroll
            for (int j = 0; j < 4; j++)
                Ps[(ty * 8 + i) * 68 + tx * 4 + j] = s[i][j];
        __syncthreads();

#pragma unroll 4
        for (int k = 0; k < 64; k++) {
            const float4 vv = *reinterpret_cast<const float4*>(Vs + k * 64 + tx * 4);
            const float bw[4] = {vv.x, vv.y, vv.z, vv.w};
            float av[8];
#pragma unroll
            for (int i = 0; i < 8; i++) av[i] = Ps[(ty * 8 + i) * 68 + k];
#pragma unroll
            for (int i = 0; i < 8; i++)
#pragma unroll
                for (int j = 0; j < 4; j++) oacc[i][j] += av[i] * bw[j];
        }
    }

    __half* Og = o + ((size_t)(b * Tn + q0)) * Cn + h * 64;
#pragma unroll
    for (int i = 0; i < 8; i++) {
        const float inv = 1.0f / l[i];
        const int r = ty * 8 + i;
        __half2* hp = reinterpret_cast<__half2*>(Og + (size_t)r * Cn + tx * 4);
        hp[0] = __floats2half2_rn(oacc[i][0] * inv, oacc[i][1] * inv);
        hp[1] = __floats2half2_rn(oacc[i][2] * inv, oacc[i][3] * inv);
    }
}

// ---------------------------------------------------------------------------
// Launch sequence
// ---------------------------------------------------------------------------
extern "C" void kernel_launch(void* const* d_in, const int* in_sizes, int n_in,
                              void* d_out, int out_size)
{
    const float* x   = (const float*)d_in[0];
    const float* Wq  = (const float*)d_in[1];
    const float* Wk  = (const float*)d_in[2];
    const float* Wv  = (const float*)d_in[3];
    const float* Wp  = (const float*)d_in[4];
    const float* bp  = (const float*)d_in[5];
    const float* W1  = (const float*)d_in[6];
    const float* b1  = (const float*)d_in[7];
    const float* W2  = (const float*)d_in[8];
    const float* b2  = (const float*)d_in[9];
    const float* g1  = (const float*)d_in[10];
    const float* be1 = (const float*)d_in[11];
    const float* g2  = (const float*)d_in[12];
    const float* be2 = (const float*)d_in[13];
    float* out = (float*)d_out;

    float *x1, *qkv, *x2, *x3;
    __half *x1h, *x3h, *oh, *hbh, *wqkvT, *wpT, *w1T, *w2T;
    cudaGetSymbolAddress((void**)&x1,    g_x1);
    cudaGetSymbolAddress((void**)&qkv,   g_qkv);
    cudaGetSymbolAddress((void**)&x2,    g_x2);
    cudaGetSymbolAddress((void**)&x3,    g_x3);
    cudaGetSymbolAddress((void**)&x1h,   g_x1h);
    cudaGetSymbolAddress((void**)&x3h,   g_x3h);
    cudaGetSymbolAddress((void**)&oh,    g_oh);
    cudaGetSymbolAddress((void**)&hbh,   g_hbh);
    cudaGetSymbolAddress((void**)&wqkvT, g_wqkvT);
    cudaGetSymbolAddress((void**)&wpT,   g_wpT);
    cudaGetSymbolAddress((void**)&w1T,   g_w1T);
    cudaGetSymbolAddress((void**)&w2T,   g_w2T);

    constexpr int GEMM_SMEM = 4 * 5120 * 2;  // 40960 B
    cudaFuncSetAttribute(hgemm_kernel<false, false, false, false>, cudaFuncAttributeMaxDynamicSharedMemorySize, GEMM_SMEM);
    cudaFuncSetAttribute(hgemm_kernel<true,  true,  false, false>, cudaFuncAttributeMaxDynamicSharedMemorySize, GEMM_SMEM);
    cudaFuncSetAttribute(hgemm_kernel<true,  false, true,  true >, cudaFuncAttributeMaxDynamicSharedMemorySize, GEMM_SMEM);

    constexpr int FLASH_SMEM = (64 * 128 + 64 * 64 + 64 * 64 + 128 * 68) * 4; // 100352 B
    cudaFuncSetAttribute(flash_kernel, cudaFuncAttributeMaxDynamicSharedMemorySize, FLASH_SMEM);

    // 1. LN1 (dual f32/f16)
    ln_kernel<<<Mn, 256>>>(x, g1, be1, x1, x1h);
    // 2. weight prep (fp16 [N][K] layouts)
    pack_wqkvT_kernel<<<dim3(4, 3072), 256>>>(Wq, Wk, Wv, wqkvT);
    transpose_kernel<<<dim3(32, 32),  dim3(32, 8)>>>(Wp, wpT, Cn, Cn);
    transpose_kernel<<<dim3(128, 32), dim3(32, 8)>>>(W1, w1T, Cn, FFn);
    transpose_kernel<<<dim3(32, 128), dim3(32, 8)>>>(W2, w2T, FFn, Cn);
    // 3. QKV GEMM: [8192,1024] @ [1024,3072] -> qkv f32
    hgemm_kernel<false, false, false, false><<<dim3(24, 64), 256, GEMM_SMEM>>>(
        x1h, wqkvT, nullptr, nullptr, qkv, nullptr, Mn, 3 * Cn, Cn);
    // 4. causal flash attention -> o f16
    flash_kernel<<<dim3(16, Hn, Bn), 256, FLASH_SMEM>>>(qkv, oh);
    // 5. proj + bias + residual(x1): x2 = x1 + o@Wp + bp
    hgemm_kernel<true, true, false, false><<<dim3(8, 64), 256, GEMM_SMEM>>>(
        oh, wpT, bp, x1, x2, nullptr, Mn, Cn, Cn);
    // 6. LN2 (dual)
    ln_kernel<<<Mn, 256>>>(x2, g2, be2, x3, x3h);
    // 7. FFN up + relu -> hb f16
    hgemm_kernel<true, false, true, true><<<dim3(32, 64), 256, GEMM_SMEM>>>(
        x3h, w1T, b1, nullptr, nullptr, hbh, Mn, FFn, Cn);
    // 8. FFN down + bias + residual(x3): out = x3 + hb@W2 + b2
    hgemm_kernel<true, true, false, false><<<dim3(8, 64), 256, GEMM_SMEM>>>(
        hbh, w2T, b2, x3, out, nullptr, Mn, Cn, FFn);
}

// round 9
// speedup vs baseline: 5.3305x; 1.7607x over previous
#include <cuda_runtime.h>
#include <cuda_fp16.h>
#include <math.h>
#include <stdint.h>

// Problem constants
#define Bn 4
#define Tn 2048
#define Cn 1024
#define Hn 16
#define HSn 64
#define Mn (Bn * Tn)        // 8192 rows
#define FFn (4 * Cn)        // 4096

// ---------------------------------------------------------------------------
// Scratch (device globals)
// ---------------------------------------------------------------------------
__device__ float  g_x1 [8388608];     // [M, C]  LN1 output (f32, residual use)
__device__ float  g_x2 [8388608];     // [M, C]
__device__ float  g_x3 [8388608];     // [M, C]
__device__ __half g_qkvh[25165824];   // [M, 3C] q|k|v (f16)
__device__ __half g_x1h[8388608];     // [M, C]  LN1 output (f16, GEMM input)
__device__ __half g_x3h[8388608];     // [M, C]  LN2 output (f16, GEMM input)
__device__ __half g_oh [8388608];     // [M, C]  attention out (f16)
__device__ __half g_hbh[33554432];    // [M, 4C] relu FFN intermediate (f16)
__device__ __half g_wqkvT[3145728];   // [3C, C] packed+transposed Wq|Wk|Wv (f16 [N][K])
__device__ __half g_wpT[1048576];     // [C, C]   Wp^T  (f16 [N][K])
__device__ __half g_w1T[4194304];     // [4C, C]  W1^T  (f16 [N][K])
__device__ __half g_w2T[4194304];     // [C, 4C]  W2^T  (f16 [N][K])

// ---------------------------------------------------------------------------
// m16n8k16 fp16 MMA helper
// ---------------------------------------------------------------------------
__device__ __forceinline__ void mma16816(float* c, uint32_t a0, uint32_t a1,
                                         uint32_t a2, uint32_t a3,
                                         uint32_t b0, uint32_t b1)
{
    asm volatile(
        "mma.sync.aligned.m16n8k16.row.col.f32.f16.f16.f32 "
        "{%0,%1,%2,%3}, {%4,%5,%6,%7}, {%8,%9}, {%0,%1,%2,%3};\n"
        : "+f"(c[0]), "+f"(c[1]), "+f"(c[2]), "+f"(c[3])
        : "r"(a0), "r"(a1), "r"(a2), "r"(a3), "r"(b0), "r"(b1));
}

__device__ __forceinline__ uint32_t packh2(float a, float b)
{
    __half2 h = __floats2half2_rn(a, b);
    return *reinterpret_cast<uint32_t*>(&h);
}

// ---------------------------------------------------------------------------
// LayerNorm (dual output: f32 + f16): one block per row
// ---------------------------------------------------------------------------
__global__ void ln_kernel(const float* __restrict__ x, const float* __restrict__ g,
                          const float* __restrict__ beta, float* __restrict__ y,
                          __half* __restrict__ yh)
{
    const int row = blockIdx.x;
    const int t = threadIdx.x;
    const float4 v = reinterpret_cast<const float4*>(x + (size_t)row * Cn)[t];
    float s = v.x + v.y + v.z + v.w;
    float q = v.x * v.x + v.y * v.y + v.z * v.z + v.w * v.w;
#pragma unroll
    for (int off = 16; off; off >>= 1) {
        s += __shfl_xor_sync(0xffffffffu, s, off);
        q += __shfl_xor_sync(0xffffffffu, q, off);
    }
    __shared__ float ss[8], qs[8];
    if ((t & 31) == 0) { ss[t >> 5] = s; qs[t >> 5] = q; }
    __syncthreads();
    s = 0.f; q = 0.f;
#pragma unroll
    for (int i = 0; i < 8; i++) { s += ss[i]; q += qs[i]; }
    const float mu = s * (1.0f / Cn);
    const float var = q * (1.0f / Cn) - mu * mu;
    const float rstd = rsqrtf(var + 1e-5f);
    const float4 gv = reinterpret_cast<const float4*>(g)[t];
    const float4 bv = reinterpret_cast<const float4*>(beta)[t];
    float4 o;
    o.x = (v.x - mu) * rstd * gv.x + bv.x;
    o.y = (v.y - mu) * rstd * gv.y + bv.y;
    o.z = (v.z - mu) * rstd * gv.z + bv.z;
    o.w = (v.w - mu) * rstd * gv.w + bv.w;
    reinterpret_cast<float4*>(y + (size_t)row * Cn)[t] = o;
    __half2* hp = reinterpret_cast<__half2*>(yh + (size_t)row * Cn + t * 4);
    hp[0] = __floats2half2_rn(o.x, o.y);
    hp[1] = __floats2half2_rn(o.z, o.w);
}

// ---------------------------------------------------------------------------
// Pack Wq/Wk/Wv into one TRANSPOSED fp16 [3C][C] matrix.
// ---------------------------------------------------------------------------
__global__ void pack_wqkvT_kernel(const float* __restrict__ Wq, const float* __restrict__ Wk,
                                  const float* __restrict__ Wv, __half* __restrict__ out)
{
    const int n = blockIdx.y;
    const int k = blockIdx.x * 256 + threadIdx.x;
    const int which = n >> 10;
    const int jj = n & 1023;
    const int h = jj >> 6, d = jj & 63;
    const float* W = (which == 0) ? Wq : (which == 1) ? Wk : Wv;
    out[(size_t)n * Cn + k] = __float2half(W[((size_t)h * Cn + k) * HSn + d]);
}

// ---------------------------------------------------------------------------
// Tiled transpose to fp16
// ---------------------------------------------------------------------------
__global__ void transpose_kernel(const float* __restrict__ in, __half* __restrict__ out,
                                 int R, int Cc)
{
    __shared__ float t[32][33];
    const int c0 = blockIdx.x * 32, r0 = blockIdx.y * 32;
    const int x = threadIdx.x, y = threadIdx.y;
#pragma unroll
    for (int i = 0; i < 32; i += 8)
        t[y + i][x] = in[(size_t)(r0 + y + i) * Cc + c0 + x];
    __syncthreads();
#pragma unroll
    for (int i = 0; i < 32; i += 8)
        out[(size_t)(c0 + y + i) * R + r0 + x] = __float2half(t[x][y + i]);
}

// ---------------------------------------------------------------------------
// fp16 tensor-core GEMM (unchanged from R8; OUTH selects fp16 output)
// ---------------------------------------------------------------------------
template <bool BIAS, bool RES, bool RELU, bool OUTH>
__global__ __launch_bounds__(256) void hgemm_kernel(
    const __half* __restrict__ A, const __half* __restrict__ Bt,
    const float* __restrict__ bias, const float* __restrict__ res,
    float* __restrict__ C, __half* __restrict__ Ch,
    int Mdim, int Ndim, int Kdim)
{
    extern __shared__ __half sm_h[];
    __half* Abuf = sm_h;
    __half* Bbuf = sm_h + 2 * 5120;

    const int tid  = threadIdx.x;
    const int lane = tid & 31;
    const int wid  = tid >> 5;
    const int warp_m = wid >> 2;
    const int warp_n = wid & 3;
    const int m0 = blockIdx.y * 128;
    const int n0 = blockIdx.x * 128;

    const int r0c = tid >> 2;
    const int ch  = (tid & 3) * 8;

    const __half* Ag = A  + (size_t)m0 * Kdim;
    const __half* Bg = Bt + (size_t)n0 * Kdim;

    uint4 ra0, ra1, rb0, rb1;
    auto gload = [&](int kt) {
        const int kb = kt * 32 + ch;
        ra0 = *reinterpret_cast<const uint4*>(Ag + (size_t)(r0c)      * Kdim + kb);
        ra1 = *reinterpret_cast<const uint4*>(Ag + (size_t)(r0c + 64) * Kdim + kb);
        rb0 = *reinterpret_cast<const uint4*>(Bg + (size_t)(r0c)      * Kdim + kb);
        rb1 = *reinterpret_cast<const uint4*>(Bg + (size_t)(r0c + 64) * Kdim + kb);
    };
    auto sstore = [&](int buf) {
        __half* Ab = Abuf + buf * 5120;
        __half* Bb = Bbuf + buf * 5120;
        *reinterpret_cast<uint4*>(Ab + (r0c)      * 40 + ch) = ra0;
        *reinterpret_cast<uint4*>(Ab + (r0c + 64) * 40 + ch) = ra1;
        *reinterpret_cast<uint4*>(Bb + (r0c)      * 40 + ch) = rb0;
        *reinterpret_cast<uint4*>(Bb + (r0c + 64) * 40 + ch) = rb1;
    };

    float acc[4][4][4];
#pragma unroll
    for (int i = 0; i < 4; i++)
#pragma unroll
        for (int j = 0; j < 4; j++)
#pragma unroll
            for (int r = 0; r < 4; r++) acc[i][j][r] = 0.f;

    gload(0);
    sstore(0);
    __syncthreads();

    const int g  = lane >> 2;
    const int t4 = lane & 3;
    const int nk = Kdim / 32;
    int buf = 0;

    for (int kt = 0; kt < nk; kt++) {
        if (kt + 1 < nk) gload(kt + 1);

        const __half* As = Abuf + buf * 5120;
        const __half* Bs = Bbuf + buf * 5120;
#pragma unroll
        for (int ks = 0; ks < 2; ks++) {
            const int kb = ks * 16 + t4 * 2;
            uint32_t a[4][4], b[4][2];
#pragma unroll
            for (int i = 0; i < 4; i++) {
                const int rA = warp_m * 64 + i * 16 + g;
                a[i][0] = *reinterpret_cast<const uint32_t*>(As + (rA)     * 40 + kb);
                a[i][1] = *reinterpret_cast<const uint32_t*>(As + (rA + 8) * 40 + kb);
                a[i][2] = *reinterpret_cast<const uint32_t*>(As + (rA)     * 40 + kb + 8);
                a[i][3] = *reinterpret_cast<const uint32_t*>(As + (rA + 8) * 40 + kb + 8);
            }
#pragma unroll
            for (int j = 0; j < 4; j++) {
                const int nB = warp_n * 32 + j * 8 + g;
                b[j][0] = *reinterpret_cast<const uint32_t*>(Bs + nB * 40 + kb);
                b[j][1] = *reinterpret_cast<const uint32_t*>(Bs + nB * 40 + kb + 8);
            }
#pragma unroll
            for (int i = 0; i < 4; i++)
#pragma unroll
                for (int j = 0; j < 4; j++)
                    mma16816(acc[i][j], a[i][0], a[i][1], a[i][2], a[i][3], b[j][0], b[j][1]);
        }

        if (kt + 1 < nk) {
            sstore(buf ^ 1);
            __syncthreads();
            buf ^= 1;
        }
    }

#pragma unroll
    for (int i = 0; i < 4; i++) {
#pragma unroll
        for (int j = 0; j < 4; j++) {
            const int col = n0 + warp_n * 32 + j * 8 + t4 * 2;
            float2 bb = {0.f, 0.f};
            if (BIAS) bb = *reinterpret_cast<const float2*>(bias + col);
#pragma unroll
            for (int half = 0; half < 2; half++) {
                const int row = m0 + warp_m * 64 + i * 16 + g + half * 8;
                float2 v;
                v.x = acc[i][j][half * 2 + 0];
                v.y = acc[i][j][half * 2 + 1];
                if (BIAS) { v.x += bb.x; v.y += bb.y; }
                if (RES) {
                    const float2 rr = *reinterpret_cast<const float2*>(res + (size_t)row * Ndim + col);
                    v.x += rr.x; v.y += rr.y;
                }
                if (RELU) { v.x = fmaxf(v.x, 0.f); v.y = fmaxf(v.y, 0.f); }
                if (OUTH) {
                    *reinterpret_cast<__half2*>(Ch + (size_t)row * Ndim + col) =
                        __floats2half2_rn(v.x, v.y);
                } else {
                    *reinterpret_cast<float2*>(C + (size_t)row * Ndim + col) = v;
                }
            }
        }
    }
}

// ---------------------------------------------------------------------------
// Tensor-core causal flash attention (fp16 MMA, fp32 softmax/acc).
// One block per (128-query tile, head, batch), 8 warps, each warp = 16 q rows.
// Q fragments live in registers the whole kernel; P repacked reg->reg.
// V transposed into smem [d][key] with xor swizzle keyed on d>>3.
// ---------------------------------------------------------------------------
#define FSTR 88   // smem row stride (halfs)

__global__ __launch_bounds__(256) void flash_h_kernel(const __half* __restrict__ qkv,
                                                      __half* __restrict__ o)
{
    __shared__ __half Qs[128 * FSTR];
    __shared__ __half Ks[64 * FSTR];
    __shared__ __half Vt[64 * FSTR];

    const int tid  = threadIdx.x;
    const int lane = tid & 31;
    const int w    = tid >> 5;
    const int g    = lane >> 2;
    const int t4   = lane & 3;

    const int qi = (int)gridDim.x - 1 - (int)blockIdx.x;  // big tiles first
    const int h  = blockIdx.y, b = blockIdx.z;
    const int q0 = qi * 128;

    const __half* Qg = qkv + ((size_t)(b * Tn + q0)) * 3072 + h * 64;
    const __half* Kg = qkv + ((size_t)(b * Tn)) * 3072 + 1024 + h * 64;
    const __half* Vg = Kg + 1024;

    // ---- load Q tile [128][64] into smem ----
#pragma unroll
    for (int u = 0; u < 4; u++) {
        const int slot = tid + 256 * u;       // 0..1023
        const int r = slot >> 3, c8 = (slot & 7) * 8;
        *reinterpret_cast<uint4*>(Qs + r * FSTR + c8) =
            *reinterpret_cast<const uint4*>(Qg + (size_t)r * 3072 + c8);
    }
    __syncthreads();

    // ---- extract Q fragments into registers (rows w*16+g, w*16+g+8) ----
    uint32_t qa[4][4];
#pragma unroll
    for (int ks = 0; ks < 4; ks++) {
        const int base = (w * 16 + g) * FSTR + ks * 16 + 2 * t4;
        qa[ks][0] = *reinterpret_cast<const uint32_t*>(Qs + base);
        qa[ks][1] = *reinterpret_cast<const uint32_t*>(Qs + base + 8 * FSTR);
        qa[ks][2] = *reinterpret_cast<const uint32_t*>(Qs + base + 8);
        qa[ks][3] = *reinterpret_cast<const uint32_t*>(Qs + base + 8 * FSTR + 8);
    }

    float oacc[8][4];
#pragma unroll
    for (int j = 0; j < 8; j++)
#pragma unroll
        for (int r = 0; r < 4; r++) oacc[j][r] = 0.f;
    float mrow[2] = {-1e30f, -1e30f};
    float lrow[2] = {0.f, 0.f};

    const int qrow0 = q0 + w * 16 + g;
    const int qrow1 = qrow0 + 8;
    const int ntiles = 2 * qi + 2;

    for (int jt = 0; jt < ntiles; jt++) {
        const int j0 = jt * 64;
        __syncthreads();  // previous PV reads done before K/V overwrite
        // ---- load K tile [64][64] and V tile transposed [d][key] ----
#pragma unroll
        for (int u = 0; u < 2; u++) {
            const int slot = tid + 256 * u;   // 0..511
            const int r = slot >> 3, c8 = (slot & 7) * 8;
            *reinterpret_cast<uint4*>(Ks + r * FSTR + c8) =
                *reinterpret_cast<const uint4*>(Kg + (size_t)(j0 + r) * 3072 + c8);
            const uint4 vv = *reinterpret_cast<const uint4*>(Vg + (size_t)(j0 + r) * 3072 + c8);
            const __half* vh = reinterpret_cast<const __half*>(&vv);
            const int keysw = r ^ c8;         // xor swizzle: ((d>>3)&7)*8 == c8
#pragma unroll
            for (int i = 0; i < 8; i++)
                Vt[(c8 + i) * FSTR + keysw] = vh[i];
        }
        __syncthreads();

        // ---- S = Q @ K^T ----
        float sacc[8][4];
#pragma unroll
        for (int j = 0; j < 8; j++)
#pragma unroll
            for (int r = 0; r < 4; r++) sacc[j][r] = 0.f;
#pragma unroll
        for (int ks = 0; ks < 4; ks++) {
            const int kb = ks * 16 + 2 * t4;
#pragma unroll
            for (int j = 0; j < 8; j++) {
                const int row = (j * 8 + g) * FSTR + kb;
                const uint32_t b0 = *reinterpret_cast<const uint32_t*>(Ks + row);
                const uint32_t b1 = *reinterpret_cast<const uint32_t*>(Ks + row + 8);
                mma16816(sacc[j], qa[ks][0], qa[ks][1], qa[ks][2], qa[ks][3], b0, b1);
            }
        }

        // ---- scale + causal mask ----
        const bool need_mask = (j0 + 63) > (q0 + w * 16);
#pragma unroll
        for (int j = 0; j < 8; j++) {
            const int c0 = j0 + j * 8 + 2 * t4;
            sacc[j][0] *= 0.03125f; sacc[j][1] *= 0.03125f;
            sacc[j][2] *= 0.03125f; sacc[j][3] *= 0.03125f;
            if (need_mask) {
                if (c0     > qrow0) sacc[j][0] = -1e30f;
                if (c0 + 1 > qrow0) sacc[j][1] = -1e30f;
                if (c0     > qrow1) sacc[j][2] = -1e30f;
                if (c0 + 1 > qrow1) sacc[j][3] = -1e30f;
            }
        }

        // ---- online softmax (two rows per thread; 4 lanes share a row) ----
#pragma unroll
        for (int r = 0; r < 2; r++) {
            float tmax = -1e30f;
#pragma unroll
            for (int j = 0; j < 8; j++)
                tmax = fmaxf(tmax, fmaxf(sacc[j][2 * r], sacc[j][2 * r + 1]));
            tmax = fmaxf(tmax, __shfl_xor_sync(0xffffffffu, tmax, 1));
            tmax = fmaxf(tmax, __shfl_xor_sync(0xffffffffu, tmax, 2));
            const float mn = fmaxf(mrow[r], tmax);
            const float corr = __expf(mrow[r] - mn);
            float rs = 0.f;
#pragma unroll
            for (int j = 0; j < 8; j++) {
                const float p0 = __expf(sacc[j][2 * r]     - mn);
                const float p1 = __expf(sacc[j][2 * r + 1] - mn);
                sacc[j][2 * r] = p0; sacc[j][2 * r + 1] = p1;
                rs += p0 + p1;
            }
            rs += __shfl_xor_sync(0xffffffffu, rs, 1);
            rs += __shfl_xor_sync(0xffffffffu, rs, 2);
            lrow[r] = lrow[r] * corr + rs;
            mrow[r] = mn;
#pragma unroll
            for (int j = 0; j < 8; j++) {
                oacc[j][2 * r]     *= corr;
                oacc[j][2 * r + 1] *= corr;
            }
        }

        // ---- repack P (S acc layout == A fragment layout) ----
        uint32_t pa[4][4];
#pragma unroll
        for (int s = 0; s < 4; s++) {
            pa[s][0] = packh2(sacc[2 * s][0],     sacc[2 * s][1]);
            pa[s][1] = packh2(sacc[2 * s][2],     sacc[2 * s][3]);
            pa[s][2] = packh2(sacc[2 * s + 1][0], sacc[2 * s + 1][1]);
            pa[s][3] = packh2(sacc[2 * s + 1][2], sacc[2 * s + 1][3]);
        }

        // ---- O += P @ V ----
#pragma unroll
        for (int s = 0; s < 4; s++) {
#pragma unroll
            for (int j = 0; j < 8; j++) {
                const int drow = (j * 8 + g) * FSTR;
                const int k0 = (s * 16 + 2 * t4) ^ (j * 8);
                const int k1 = (s * 16 + 8 + 2 * t4) ^ (j * 8);
                const uint32_t b0 = *reinterpret_cast<const uint32_t*>(Vt + drow + k0);
                const uint32_t b1 = *reinterpret_cast<const uint32_t*>(Vt + drow + k1);
                mma16816(oacc[j], pa[s][0], pa[s][1], pa[s][2], pa[s][3], b0, b1);
            }
        }
    }

    // ---- normalize + write ----
    const float inv0 = 1.0f / lrow[0];
    const float inv1 = 1.0f / lrow[1];
    __half* Og = o + ((size_t)(b * Tn + q0 + w * 16 + g)) * Cn + h * 64;
#pragma unroll
    for (int j = 0; j < 8; j++) {
        const int dc = j * 8 + 2 * t4;
        *reinterpret_cast<__half2*>(Og + dc) =
            __floats2half2_rn(oacc[j][0] * inv0, oacc[j][1] * inv0);
        *reinterpret_cast<__half2*>(Og + 8 * (size_t)Cn + dc) =
            __floats2half2_rn(oacc[j][2] * inv1, oacc[j][3] * inv1);
    }
}

// ---------------------------------------------------------------------------
// Launch sequence
// ---------------------------------------------------------------------------
extern "C" void kernel_launch(void* const* d_in, const int* in_sizes, int n_in,
                              void* d_out, int out_size)
{
    const float* x   = (const float*)d_in[0];
    const float* Wq  = (const float*)d_in[1];
    const float* Wk  = (const float*)d_in[2];
    const float* Wv  = (const float*)d_in[3];
    const float* Wp  = (const float*)d_in[4];
    const float* bp  = (const float*)d_in[5];
    const float* W1  = (const float*)d_in[6];
    const float* b1  = (const float*)d_in[7];
    const float* W2  = (const float*)d_in[8];
    const float* b2  = (const float*)d_in[9];
    const float* g1  = (const float*)d_in[10];
    const float* be1 = (const float*)d_in[11];
    const float* g2  = (const float*)d_in[12];
    const float* be2 = (const float*)d_in[13];
    float* out = (float*)d_out;

    float *x1, *x2, *x3;
    __half *qkvh, *x1h, *x3h, *oh, *hbh, *wqkvT, *wpT, *w1T, *w2T;
    cudaGetSymbolAddress((void**)&x1,    g_x1);
    cudaGetSymbolAddress((void**)&x2,    g_x2);
    cudaGetSymbolAddress((void**)&x3,    g_x3);
    cudaGetSymbolAddress((void**)&qkvh,  g_qkvh);
    cudaGetSymbolAddress((void**)&x1h,   g_x1h);
    cudaGetSymbolAddress((void**)&x3h,   g_x3h);
    cudaGetSymbolAddress((void**)&oh,    g_oh);
    cudaGetSymbolAddress((void**)&hbh,   g_hbh);
    cudaGetSymbolAddress((void**)&wqkvT, g_wqkvT);
    cudaGetSymbolAddress((void**)&wpT,   g_wpT);
    cudaGetSymbolAddress((void**)&w1T,   g_w1T);
    cudaGetSymbolAddress((void**)&w2T,   g_w2T);

    constexpr int GEMM_SMEM = 4 * 5120 * 2;  // 40960 B
    cudaFuncSetAttribute(hgemm_kernel<false, false, false, true >, cudaFuncAttributeMaxDynamicSharedMemorySize, GEMM_SMEM);
    cudaFuncSetAttribute(hgemm_kernel<true,  true,  false, false>, cudaFuncAttributeMaxDynamicSharedMemorySize, GEMM_SMEM);
    cudaFuncSetAttribute(hgemm_kernel<true,  false, true,  true >, cudaFuncAttributeMaxDynamicSharedMemorySize, GEMM_SMEM);

    // 1. LN1 (dual f32/f16)
    ln_kernel<<<Mn, 256>>>(x, g1, be1, x1, x1h);
    // 2. weight prep (fp16 [N][K] layouts)
    pack_wqkvT_kernel<<<dim3(4, 3072), 256>>>(Wq, Wk, Wv, wqkvT);
    transpose_kernel<<<dim3(32, 32),  dim3(32, 8)>>>(Wp, wpT, Cn, Cn);
    transpose_kernel<<<dim3(128, 32), dim3(32, 8)>>>(W1, w1T, Cn, FFn);
    transpose_kernel<<<dim3(32, 128), dim3(32, 8)>>>(W2, w2T, FFn, Cn);
    // 3. QKV GEMM -> qkv f16
    hgemm_kernel<false, false, false, true><<<dim3(24, 64), 256, GEMM_SMEM>>>(
        x1h, wqkvT, nullptr, nullptr, nullptr, qkvh, Mn, 3 * Cn, Cn);
    // 4. tensor-core causal flash attention -> o f16
    flash_h_kernel<<<dim3(16, Hn, Bn), 256>>>(qkvh, oh);
    // 5. proj + bias + residual(x1): x2 = x1 + o@Wp + bp
    hgemm_kernel<true, true, false, false><<<dim3(8, 64), 256, GEMM_SMEM>>>(
        oh, wpT, bp, x1, x2, nullptr, Mn, Cn, Cn);
    // 6. LN2 (dual)
    ln_kernel<<<Mn, 256>>>(x2, g2, be2, x3, x3h);
    // 7. FFN up + relu -> hb f16
    hgemm_kernel<true, false, true, true><<<dim3(32, 64), 256, GEMM_SMEM>>>(
        x3h, w1T, b1, nullptr, nullptr, hbh, Mn, FFn, Cn);
    // 8. FFN down + bias + residual(x3): out = x3 + hb@W2 + b2
    hgemm_kernel<true, true, false, false><<<dim3(8, 64), 256, GEMM_SMEM>>>(
        hbh, w2T, b2, x3, out, nullptr, Mn, Cn, FFn);
}

// round 10
// speedup vs baseline: 6.0790x; 1.1404x over previous
#include <cuda_runtime.h>
#include <cuda_fp16.h>
#include <math.h>
#include <stdint.h>

// Problem constants
#define Bn 4
#define Tn 2048
#define Cn 1024
#define Hn 16
#define HSn 64
#define Mn (Bn * Tn)        // 8192 rows
#define FFn (4 * Cn)        // 4096

// ---------------------------------------------------------------------------
// Scratch (device globals)
// ---------------------------------------------------------------------------
__device__ float  g_x1 [8388608];     // [M, C]  LN1 output (f32, residual use)
__device__ float  g_x2 [8388608];     // [M, C]
__device__ float  g_x3 [8388608];     // [M, C]
__device__ __half g_qkvh[25165824];   // [M, 3C] q|k|v (f16)
__device__ __half g_x1h[8388608];     // [M, C]  LN1 output (f16, GEMM input)
__device__ __half g_x3h[8388608];     // [M, C]  LN2 output (f16, GEMM input)
__device__ __half g_oh [8388608];     // [M, C]  attention out (f16)
__device__ __half g_hbh[33554432];    // [M, 4C] relu FFN intermediate (f16)
__device__ __half g_wqkvT[3145728];   // [3C, C] packed+transposed Wq|Wk|Wv (f16 [N][K])
__device__ __half g_wpT[1048576];     // [C, C]   Wp^T  (f16 [N][K])
__device__ __half g_w1T[4194304];     // [4C, C]  W1^T  (f16 [N][K])
__device__ __half g_w2T[4194304];     // [C, 4C]  W2^T  (f16 [N][K])

// ---------------------------------------------------------------------------
// helpers
// ---------------------------------------------------------------------------
__device__ __forceinline__ void mma16816(float* c, uint32_t a0, uint32_t a1,
                                         uint32_t a2, uint32_t a3,
                                         uint32_t b0, uint32_t b1)
{
    asm volatile(
        "mma.sync.aligned.m16n8k16.row.col.f32.f16.f16.f32 "
        "{%0,%1,%2,%3}, {%4,%5,%6,%7}, {%8,%9}, {%0,%1,%2,%3};\n"
        : "+f"(c[0]), "+f"(c[1]), "+f"(c[2]), "+f"(c[3])
        : "r"(a0), "r"(a1), "r"(a2), "r"(a3), "r"(b0), "r"(b1));
}

__device__ __forceinline__ uint32_t packh2(float a, float b)
{
    __half2 h = __floats2half2_rn(a, b);
    return *reinterpret_cast<uint32_t*>(&h);
}

__device__ __forceinline__ void cp16(void* smem_dst, const void* gsrc)
{
    uint32_t d = (uint32_t)__cvta_generic_to_shared(smem_dst);
    asm volatile("cp.async.cg.shared.global [%0], [%1], 16;\n" :: "r"(d), "l"(gsrc));
}
#define CP_COMMIT() asm volatile("cp.async.commit_group;" ::: "memory")
#define CP_WAIT1()  asm volatile("cp.async.wait_group 1;" ::: "memory")

// ---------------------------------------------------------------------------
// LayerNorm (dual output: f32 + f16): one block per row
// ---------------------------------------------------------------------------
__global__ void ln_kernel(const float* __restrict__ x, const float* __restrict__ g,
                          const float* __restrict__ beta, float* __restrict__ y,
                          __half* __restrict__ yh)
{
    const int row = blockIdx.x;
    const int t = threadIdx.x;
    const float4 v = reinterpret_cast<const float4*>(x + (size_t)row * Cn)[t];
    float s = v.x + v.y + v.z + v.w;
    float q = v.x * v.x + v.y * v.y + v.z * v.z + v.w * v.w;
#pragma unroll
    for (int off = 16; off; off >>= 1) {
        s += __shfl_xor_sync(0xffffffffu, s, off);
        q += __shfl_xor_sync(0xffffffffu, q, off);
    }
    __shared__ float ss[8], qs[8];
    if ((t & 31) == 0) { ss[t >> 5] = s; qs[t >> 5] = q; }
    __syncthreads();
    s = 0.f; q = 0.f;
#pragma unroll
    for (int i = 0; i < 8; i++) { s += ss[i]; q += qs[i]; }
    const float mu = s * (1.0f / Cn);
    const float var = q * (1.0f / Cn) - mu * mu;
    const float rstd = rsqrtf(var + 1e-5f);
    const float4 gv = reinterpret_cast<const float4*>(g)[t];
    const float4 bv = reinterpret_cast<const float4*>(beta)[t];
    float4 o;
    o.x = (v.x - mu) * rstd * gv.x + bv.x;
    o.y = (v.y - mu) * rstd * gv.y + bv.y;
    o.z = (v.z - mu) * rstd * gv.z + bv.z;
    o.w = (v.w - mu) * rstd * gv.w + bv.w;
    reinterpret_cast<float4*>(y + (size_t)row * Cn)[t] = o;
    __half2* hp = reinterpret_cast<__half2*>(yh + (size_t)row * Cn + t * 4);
    hp[0] = __floats2half2_rn(o.x, o.y);
    hp[1] = __floats2half2_rn(o.z, o.w);
}

// ---------------------------------------------------------------------------
// Pack Wq/Wk/Wv into one TRANSPOSED fp16 [3C][C] matrix.
// ---------------------------------------------------------------------------
__global__ void pack_wqkvT_kernel(const float* __restrict__ Wq, const float* __restrict__ Wk,
                                  const float* __restrict__ Wv, __half* __restrict__ out)
{
    const int n = blockIdx.y;
    const int k = blockIdx.x * 256 + threadIdx.x;
    const int which = n >> 10;
    const int jj = n & 1023;
    const int h = jj >> 6, d = jj & 63;
    const float* W = (which == 0) ? Wq : (which == 1) ? Wk : Wv;
    out[(size_t)n * Cn + k] = __float2half(W[((size_t)h * Cn + k) * HSn + d]);
}

// ---------------------------------------------------------------------------
// Tiled transpose to fp16
// ---------------------------------------------------------------------------
__global__ void transpose_kernel(const float* __restrict__ in, __half* __restrict__ out,
                                 int R, int Cc)
{
    __shared__ float t[32][33];
    const int c0 = blockIdx.x * 32, r0 = blockIdx.y * 32;
    const int x = threadIdx.x, y = threadIdx.y;
#pragma unroll
    for (int i = 0; i < 32; i += 8)
        t[y + i][x] = in[(size_t)(r0 + y + i) * Cc + c0 + x];
    __syncthreads();
#pragma unroll
    for (int i = 0; i < 32; i += 8)
        out[(size_t)(c0 + y + i) * R + r0 + x] = __float2half(t[x][y + i]);
}

// ---------------------------------------------------------------------------
// fp16 tensor-core GEMM with 3-stage cp.async pipeline.
// C[M,N] = A[M,K] @ Bt[N,K]^T (+bias)(+res)(relu)
// 128x128x32 block tile, 8 warps (2x4), warp tile 64x32, mma.sync.m16n8k16.
// Smem rows padded to 40 halfs (conflict-free 32-bit fragment loads).
// Requires M%128==0, N%128==0, K%96>=... (nk >= 3; all our K are 1024/4096).
// ---------------------------------------------------------------------------
template <bool BIAS, bool RES, bool RELU, bool OUTH>
__global__ __launch_bounds__(256) void hgemm_kernel(
    const __half* __restrict__ A, const __half* __restrict__ Bt,
    const float* __restrict__ bias, const float* __restrict__ res,
    float* __restrict__ C, __half* __restrict__ Ch,
    int Mdim, int Ndim, int Kdim)
{
    extern __shared__ __half sm_h[];   // 3 stages x (A 5120 + B 5120) halfs

    const int tid  = threadIdx.x;
    const int lane = tid & 31;
    const int wid  = tid >> 5;
    const int warp_m = wid >> 2;
    const int warp_n = wid & 3;
    const int m0 = blockIdx.y * 128;
    const int n0 = blockIdx.x * 128;

    const int r0c = tid >> 2;          // 0..63
    const int ch  = (tid & 3) * 8;     // 0,8,16,24 (halfs)

    const __half* Ag = A  + (size_t)m0 * Kdim + ch;
    const __half* Bg = Bt + (size_t)n0 * Kdim + ch;

    auto load_stage = [&](int kt, int s) {
        __half* Ab = sm_h + s * 10240;
        __half* Bb = Ab + 5120;
        const size_t kb = (size_t)kt * 32;
        cp16(Ab + (r0c)      * 40 + ch, Ag + (size_t)(r0c)      * Kdim + kb);
        cp16(Ab + (r0c + 64) * 40 + ch, Ag + (size_t)(r0c + 64) * Kdim + kb);
        cp16(Bb + (r0c)      * 40 + ch, Bg + (size_t)(r0c)      * Kdim + kb);
        cp16(Bb + (r0c + 64) * 40 + ch, Bg + (size_t)(r0c + 64) * Kdim + kb);
    };

    float acc[4][4][4];
#pragma unroll
    for (int i = 0; i < 4; i++)
#pragma unroll
        for (int j = 0; j < 4; j++)
#pragma unroll
            for (int r = 0; r < 4; r++) acc[i][j][r] = 0.f;

    const int nk = Kdim / 32;   // >= 32 for our shapes

    // pipeline prologue: stages 0,1 in flight
    load_stage(0, 0); CP_COMMIT();
    load_stage(1, 1); CP_COMMIT();

    const int g  = lane >> 2;
    const int t4 = lane & 3;

    int stage = 0;
    for (int kt = 0; kt < nk; kt++) {
        CP_WAIT1();          // stage kt resident
        __syncthreads();     // all warps done with stage (kt-1) compute & see kt data

        // issue loads for stage kt+2 (overwrites stage (kt-1)%3 -- safe after sync)
        if (kt + 2 < nk) load_stage(kt + 2, (kt + 2) % 3);
        CP_COMMIT();

        const __half* As = sm_h + stage * 10240;
        const __half* Bs = As + 5120;
#pragma unroll
        for (int ks = 0; ks < 2; ks++) {
            const int kb = ks * 16 + t4 * 2;
            uint32_t a[4][4], b[4][2];
#pragma unroll
            for (int i = 0; i < 4; i++) {
                const int rA = warp_m * 64 + i * 16 + g;
                a[i][0] = *reinterpret_cast<const uint32_t*>(As + (rA)     * 40 + kb);
                a[i][1] = *reinterpret_cast<const uint32_t*>(As + (rA + 8) * 40 + kb);
                a[i][2] = *reinterpret_cast<const uint32_t*>(As + (rA)     * 40 + kb + 8);
                a[i][3] = *reinterpret_cast<const uint32_t*>(As + (rA + 8) * 40 + kb + 8);
            }
#pragma unroll
            for (int j = 0; j < 4; j++) {
                const int nB = warp_n * 32 + j * 8 + g;
                b[j][0] = *reinterpret_cast<const uint32_t*>(Bs + nB * 40 + kb);
                b[j][1] = *reinterpret_cast<const uint32_t*>(Bs + nB * 40 + kb + 8);
            }
#pragma unroll
            for (int i = 0; i < 4; i++)
#pragma unroll
                for (int j = 0; j < 4; j++)
                    mma16816(acc[i][j], a[i][0], a[i][1], a[i][2], a[i][3], b[j][0], b[j][1]);
        }
        stage = (stage + 1 == 3) ? 0 : stage + 1;
    }

    // ---- epilogue (m16n8 acc layout) ----
#pragma unroll
    for (int i = 0; i < 4; i++) {
#pragma unroll
        for (int j = 0; j < 4; j++) {
            const int col = n0 + warp_n * 32 + j * 8 + t4 * 2;
            float2 bb = {0.f, 0.f};
            if (BIAS) bb = *reinterpret_cast<const float2*>(bias + col);
#pragma unroll
            for (int half = 0; half < 2; half++) {
                const int row = m0 + warp_m * 64 + i * 16 + g + half * 8;
                float2 v;
                v.x = acc[i][j][half * 2 + 0];
                v.y = acc[i][j][half * 2 + 1];
                if (BIAS) { v.x += bb.x; v.y += bb.y; }
                if (RES) {
                    const float2 rr = *reinterpret_cast<const float2*>(res + (size_t)row * Ndim + col);
                    v.x += rr.x; v.y += rr.y;
                }
                if (RELU) { v.x = fmaxf(v.x, 0.f); v.y = fmaxf(v.y, 0.f); }
                if (OUTH) {
                    *reinterpret_cast<__half2*>(Ch + (size_t)row * Ndim + col) =
                        __floats2half2_rn(v.x, v.y);
                } else {
                    *reinterpret_cast<float2*>(C + (size_t)row * Ndim + col) = v;
                }
            }
        }
    }
}

// ---------------------------------------------------------------------------
// Tensor-core causal flash attention (fp16 MMA, fp32 softmax/acc).
// ---------------------------------------------------------------------------
#define FSTR 88   // smem row stride (halfs)

__global__ __launch_bounds__(256) void flash_h_kernel(const __half* __restrict__ qkv,
                                                      __half* __restrict__ o)
{
    __shared__ __half Qs[128 * FSTR];
    __shared__ __half Ks[64 * FSTR];
    __shared__ __half Vt[64 * FSTR];

    const int tid  = threadIdx.x;
    const int lane = tid & 31;
    const int w    = tid >> 5;
    const int g    = lane >> 2;
    const int t4   = lane & 3;

    const int qi = (int)gridDim.x - 1 - (int)blockIdx.x;  // big tiles first
    const int h  = blockIdx.y, b = blockIdx.z;
    const int q0 = qi * 128;

    const __half* Qg = qkv + ((size_t)(b * Tn + q0)) * 3072 + h * 64;
    const __half* Kg = qkv + ((size_t)(b * Tn)) * 3072 + 1024 + h * 64;
    const __half* Vg = Kg + 1024;

#pragma unroll
    for (int u = 0; u < 4; u++) {
        const int slot = tid + 256 * u;
        const int r = slot >> 3, c8 = (slot & 7) * 8;
        *reinterpret_cast<uint4*>(Qs + r * FSTR + c8) =
            *reinterpret_cast<const uint4*>(Qg + (size_t)r * 3072 + c8);
    }
    __syncthreads();

    uint32_t qa[4][4];
#pragma unroll
    for (int ks = 0; ks < 4; ks++) {
        const int base = (w * 16 + g) * FSTR + ks * 16 + 2 * t4;
        qa[ks][0] = *reinterpret_cast<const uint32_t*>(Qs + base);
        qa[ks][1] = *reinterpret_cast<const uint32_t*>(Qs + base + 8 * FSTR);
        qa[ks][2] = *reinterpret_cast<const uint32_t*>(Qs + base + 8);
        qa[ks][3] = *reinterpret_cast<const uint32_t*>(Qs + base + 8 * FSTR + 8);
    }

    float oacc[8][4];
#pragma unroll
    for (int j = 0; j < 8; j++)
#pragma unroll
        for (int r = 0; r < 4; r++) oacc[j][r] = 0.f;
    float mrow[2] = {-1e30f, -1e30f};
    float lrow[2] = {0.f, 0.f};

    const int qrow0 = q0 + w * 16 + g;
    const int qrow1 = qrow0 + 8;
    const int ntiles = 2 * qi + 2;

    for (int jt = 0; jt < ntiles; jt++) {
        const int j0 = jt * 64;
        __syncthreads();
#pragma unroll
        for (int u = 0; u < 2; u++) {
            const int slot = tid + 256 * u;
            const int r = slot >> 3, c8 = (slot & 7) * 8;
            *reinterpret_cast<uint4*>(Ks + r * FSTR + c8) =
                *reinterpret_cast<const uint4*>(Kg + (size_t)(j0 + r) * 3072 + c8);
            const uint4 vv = *reinterpret_cast<const uint4*>(Vg + (size_t)(j0 + r) * 3072 + c8);
            const __half* vh = reinterpret_cast<const __half*>(&vv);
            const int keysw = r ^ c8;
#pragma unroll
            for (int i = 0; i < 8; i++)
                Vt[(c8 + i) * FSTR + keysw] = vh[i];
        }
        __syncthreads();

        float sacc[8][4];
#pragma unroll
        for (int j = 0; j < 8; j++)
#pragma unroll
            for (int r = 0; r < 4; r++) sacc[j][r] = 0.f;
#pragma unroll
        for (int ks = 0; ks < 4; ks++) {
            const int kb = ks * 16 + 2 * t4;
#pragma unroll
            for (int j = 0; j < 8; j++) {
                const int row = (j * 8 + g) * FSTR + kb;
                const uint32_t b0 = *reinterpret_cast<const uint32_t*>(Ks + row);
                const uint32_t b1 = *reinterpret_cast<const uint32_t*>(Ks + row + 8);
                mma16816(sacc[j], qa[ks][0], qa[ks][1], qa[ks][2], qa[ks][3], b0, b1);
            }
        }

        const bool need_mask = (j0 + 63) > (q0 + w * 16);
#pragma unroll
        for (int j = 0; j < 8; j++) {
            const int c0 = j0 + j * 8 + 2 * t4;
            sacc[j][0] *= 0.03125f; sacc[j][1] *= 0.03125f;
            sacc[j][2] *= 0.03125f; sacc[j][3] *= 0.03125f;
            if (need_mask) {
                if (c0     > qrow0) sacc[j][0] = -1e30f;
                if (c0 + 1 > qrow0) sacc[j][1] = -1e30f;
                if (c0     > qrow1) sacc[j][2] = -1e30f;
                if (c0 + 1 > qrow1) sacc[j][3] = -1e30f;
            }
        }

#pragma unroll
        for (int r = 0; r < 2; r++) {
            float tmax = -1e30f;
#pragma unroll
            for (int j = 0; j < 8; j++)
                tmax = fmaxf(tmax, fmaxf(sacc[j][2 * r], sacc[j][2 * r + 1]));
            tmax = fmaxf(tmax, __shfl_xor_sync(0xffffffffu, tmax, 1));
            tmax = fmaxf(tmax, __shfl_xor_sync(0xffffffffu, tmax, 2));
            const float mn = fmaxf(mrow[r], tmax);
            const float corr = __expf(mrow[r] - mn);
            float rs = 0.f;
#pragma unroll
            for (int j = 0; j < 8; j++) {
                const float p0 = __expf(sacc[j][2 * r]     - mn);
                const float p1 = __expf(sacc[j][2 * r + 1] - mn);
                sacc[j][2 * r] = p0; sacc[j][2 * r + 1] = p1;
                rs += p0 + p1;
            }
            rs += __shfl_xor_sync(0xffffffffu, rs, 1);
            rs += __shfl_xor_sync(0xffffffffu, rs, 2);
            lrow[r] = lrow[r] * corr + rs;
            mrow[r] = mn;
#pragma unroll
            for (int j = 0; j < 8; j++) {
                oacc[j][2 * r]     *= corr;
                oacc[j][2 * r + 1] *= corr;
            }
        }

        uint32_t pa[4][4];
#pragma unroll
        for (int s = 0; s < 4; s++) {
            pa[s][0] = packh2(sacc[2 * s][0],     sacc[2 * s][1]);
            pa[s][1] = packh2(sacc[2 * s][2],     sacc[2 * s][3]);
            pa[s][2] = packh2(sacc[2 * s + 1][0], sacc[2 * s + 1][1]);
            pa[s][3] = packh2(sacc[2 * s + 1][2], sacc[2 * s + 1][3]);
        }

#pragma unroll
        for (int s = 0; s < 4; s++) {
#pragma unroll
            for (int j = 0; j < 8; j++) {
                const int drow = (j * 8 + g) * FSTR;
                const int k0 = (s * 16 + 2 * t4) ^ (j * 8);
                const int k1 = (s * 16 + 8 + 2 * t4) ^ (j * 8);
                const uint32_t b0 = *reinterpret_cast<const uint32_t*>(Vt + drow + k0);
                const uint32_t b1 = *reinterpret_cast<const uint32_t*>(Vt + drow + k1);
                mma16816(oacc[j], pa[s][0], pa[s][1], pa[s][2], pa[s][3], b0, b1);
            }
        }
    }

    const float inv0 = 1.0f / lrow[0];
    const float inv1 = 1.0f / lrow[1];
    __half* Og = o + ((size_t)(b * Tn + q0 + w * 16 + g)) * Cn + h * 64;
#pragma unroll
    for (int j = 0; j < 8; j++) {
        const int dc = j * 8 + 2 * t4;
        *reinterpret_cast<__half2*>(Og + dc) =
            __floats2half2_rn(oacc[j][0] * inv0, oacc[j][1] * inv0);
        *reinterpret_cast<__half2*>(Og + 8 * (size_t)Cn + dc) =
            __floats2half2_rn(oacc[j][2] * inv1, oacc[j][3] * inv1);
    }
}

// ---------------------------------------------------------------------------
// Launch sequence
// ---------------------------------------------------------------------------
extern "C" void kernel_launch(void* const* d_in, const int* in_sizes, int n_in,
                              void* d_out, int out_size)
{
    const float* x   = (const float*)d_in[0];
    const float* Wq  = (const float*)d_in[1];
    const float* Wk  = (const float*)d_in[2];
    const float* Wv  = (const float*)d_in[3];
    const float* Wp  = (const float*)d_in[4];
    const float* bp  = (const float*)d_in[5];
    const float* W1  = (const float*)d_in[6];
    const float* b1  = (const float*)d_in[7];
    const float* W2  = (const float*)d_in[8];
    const float* b2  = (const float*)d_in[9];
    const float* g1  = (const float*)d_in[10];
    const float* be1 = (const float*)d_in[11];
    const float* g2  = (const float*)d_in[12];
    const float* be2 = (const float*)d_in[13];
    float* out = (float*)d_out;

    float *x1, *x2, *x3;
    __half *qkvh, *x1h, *x3h, *oh, *hbh, *wqkvT, *wpT, *w1T, *w2T;
    cudaGetSymbolAddress((void**)&x1,    g_x1);
    cudaGetSymbolAddress((void**)&x2,    g_x2);
    cudaGetSymbolAddress((void**)&x3,    g_x3);
    cudaGetSymbolAddress((void**)&qkvh,  g_qkvh);
    cudaGetSymbolAddress((void**)&x1h,   g_x1h);
    cudaGetSymbolAddress((void**)&x3h,   g_x3h);
    cudaGetSymbolAddress((void**)&oh,    g_oh);
    cudaGetSymbolAddress((void**)&hbh,   g_hbh);
    cudaGetSymbolAddress((void**)&wqkvT, g_wqkvT);
    cudaGetSymbolAddress((void**)&wpT,   g_wpT);
    cudaGetSymbolAddress((void**)&w1T,   g_w1T);
    cudaGetSymbolAddress((void**)&w2T,   g_w2T);

    constexpr int GEMM_SMEM = 3 * 10240 * 2;  // 61440 B (3 stages x (A+B))
    cudaFuncSetAttribute(hgemm_kernel<false, false, false, true >, cudaFuncAttributeMaxDynamicSharedMemorySize, GEMM_SMEM);
    cudaFuncSetAttribute(hgemm_kernel<true,  true,  false, false>, cudaFuncAttributeMaxDynamicSharedMemorySize, GEMM_SMEM);
    cudaFuncSetAttribute(hgemm_kernel<true,  false, true,  true >, cudaFuncAttributeMaxDynamicSharedMemorySize, GEMM_SMEM);

    // 1. LN1 (dual f32/f16)
    ln_kernel<<<Mn, 256>>>(x, g1, be1, x1, x1h);
    // 2. weight prep (fp16 [N][K] layouts)
    pack_wqkvT_kernel<<<dim3(4, 3072), 256>>>(Wq, Wk, Wv, wqkvT);
    transpose_kernel<<<dim3(32, 32),  dim3(32, 8)>>>(Wp, wpT, Cn, Cn);
    transpose_kernel<<<dim3(128, 32), dim3(32, 8)>>>(W1, w1T, Cn, FFn);
    transpose_kernel<<<dim3(32, 128), dim3(32, 8)>>>(W2, w2T, FFn, Cn);
    // 3. QKV GEMM -> qkv f16
    hgemm_kernel<false, false, false, true><<<dim3(24, 64), 256, GEMM_SMEM>>>(
        x1h, wqkvT, nullptr, nullptr, nullptr, qkvh, Mn, 3 * Cn, Cn);
    // 4. tensor-core causal flash attention -> o f16
    flash_h_kernel<<<dim3(16, Hn, Bn), 256>>>(qkvh, oh);
    // 5. proj + bias + residual(x1): x2 = x1 + o@Wp + bp
    hgemm_kernel<true, true, false, false><<<dim3(8, 64), 256, GEMM_SMEM>>>(
        oh, wpT, bp, x1, x2, nullptr, Mn, Cn, Cn);
    // 6. LN2 (dual)
    ln_kernel<<<Mn, 256>>>(x2, g2, be2, x3, x3h);
    // 7. FFN up + relu -> hb f16
    hgemm_kernel<true, false, true, true><<<dim3(32, 64), 256, GEMM_SMEM>>>(
        x3h, w1T, b1, nullptr, nullptr, hbh, Mn, FFn, Cn);
    // 8. FFN down + bias + residual(x3): out = x3 + hb@W2 + b2
    hgemm_kernel<true, true, false, false><<<dim3(8, 64), 256, GEMM_SMEM>>>(
        hbh, w2T, b2, x3, out, nullptr, Mn, Cn, FFn);
}